// round 15
// baseline (speedup 1.0000x reference)
#include <cuda_runtime.h>
#include <cuda_bf16.h>
#include <math.h>
#include <stdint.h>
#include <stddef.h>

// ---------------- problem constants ----------------
#define NUM_B 4
#define SEQ   2048
#define DIM   512
#define NH    8
#define DHD   64
#define FF    2048
#define ROWS  (NUM_B*SEQ)          // 8192
#define NLAYER 2

// output layout (float32, concatenated in reference return order)
#define OFF_XT   0
#define N_XT     (ROWS*DIM)                 // 4194304
#define OFF_IDS  (OFF_XT + N_XT)            // 4194304
#define N_IDS    (ROWS)                     // 8192
#define OFF_ACL  (OFF_IDS + N_IDS)          // 4202496
#define OFF_MASK (OFF_ACL + 1)              // 4202497 (odd -> scalar stores only)
#define N_MASK   (NUM_B*SEQ*SEQ)            // 16777216
#define OFF_CLL  (OFF_MASK + N_MASK)        // 20979713

// per-layer transposed-weight bf16 buffer layout (elements)
#define WT_Q   0
#define WT_K   (512*512)
#define WT_V   (2*512*512)
#define WT_O   (3*512*512)
#define WT_W1  (4*512*512)                  // [2048][512]
#define WT_W2  (4*512*512 + 2048*512)       // [512][2048]
#define WT_LAYER (4*512*512 + 2*2048*512)   // 3145728

// ---------------- scratch (device globals; no allocation allowed) ----------------
__device__ float g_X [ROWS*DIM];
__device__ __nv_bfloat16 g_Qbh[ROWS*DIM];   // (B,H,S,Dh) hi, pre-scaled 1/8
__device__ __nv_bfloat16 g_Qbl[ROWS*DIM];
__device__ __nv_bfloat16 g_Kbh[ROWS*DIM];   // (B,H,S,Dh)
__device__ __nv_bfloat16 g_Kbl[ROWS*DIM];
__device__ __nv_bfloat16 g_Vbh[ROWS*DIM];   // (B,H,Dh,S)
__device__ __nv_bfloat16 g_Vbl[ROWS*DIM];
__device__ __nv_bfloat16 g_Ahi[ROWS*DIM];
__device__ __nv_bfloat16 g_Alo[ROWS*DIM];
__device__ __nv_bfloat16 g_Ghi[ROWS*FF];
__device__ __nv_bfloat16 g_Glo[ROWS*FF];
__device__ __nv_bfloat16 g_WThi[NLAYER*WT_LAYER];
__device__ __nv_bfloat16 g_WTlo[NLAYER*WT_LAYER];
__device__ float g_probs[ROWS];
__device__ int   g_ids[ROWS];
__device__ int   g_nch[NUM_B];
__device__ float g_psum[NUM_B];
__device__ float g_rc[SEQ*32];
__device__ float g_rs[SEQ*32];

// ---------------- low-level helpers ----------------
__device__ __forceinline__ void mma16816(float* c, const uint32_t* a, const uint32_t* b) {
    asm volatile(
        "mma.sync.aligned.m16n8k16.row.col.f32.bf16.bf16.f32 "
        "{%0,%1,%2,%3}, {%4,%5,%6,%7}, {%8,%9}, {%0,%1,%2,%3};"
        : "+f"(c[0]), "+f"(c[1]), "+f"(c[2]), "+f"(c[3])
        : "r"(a[0]), "r"(a[1]), "r"(a[2]), "r"(a[3]), "r"(b[0]), "r"(b[1]));
}

__device__ __forceinline__ uint32_t pack_bf16x2(float x, float y) {
    __nv_bfloat162 t;
    t.x = __float2bfloat16(x);
    t.y = __float2bfloat16(y);
    return *(uint32_t*)&t;
}

__device__ __forceinline__ uint32_t smem_u32(const void* p) {
    uint32_t a;
    asm("{ .reg .u64 t; cvta.to.shared.u64 t, %1; cvt.u32.u64 %0, t; }" : "=r"(a) : "l"(p));
    return a;
}

__device__ __forceinline__ void cp_async16(uint32_t saddr, const void* gaddr) {
    asm volatile("cp.async.ca.shared.global [%0], [%1], 16;" :: "r"(saddr), "l"(gaddr));
}
#define CP_COMMIT() asm volatile("cp.async.commit_group;" ::: "memory")
#define CP_WAIT1()  asm volatile("cp.async.wait_group 1;" ::: "memory")
#define CP_WAIT0()  asm volatile("cp.async.wait_group 0;" ::: "memory")

__device__ __forceinline__ void ldsm_x4(uint32_t* r, uint32_t saddr) {
    asm volatile("ldmatrix.sync.aligned.m8n8.x4.shared.b16 {%0,%1,%2,%3}, [%4];"
        : "=r"(r[0]), "=r"(r[1]), "=r"(r[2]), "=r"(r[3]) : "r"(saddr));
}
__device__ __forceinline__ void ldsm_x2(uint32_t* r, uint32_t saddr) {
    asm volatile("ldmatrix.sync.aligned.m8n8.x2.shared.b16 {%0,%1}, [%2];"
        : "=r"(r[0]), "=r"(r[1]) : "r"(saddr));
}

// ---------------- GEMM mainloop (R9 staging; B-operand now ldsm.x4) -------
#define SKP 40                       // padded smem row stride (elements); 80B
#define GBUF (128*SKP)               // elements per operand buffer
#define GSTAGE (4*GBUF)              // elements per stage (Ah,Al,Bh,Bl)
#define GM_SMEM2 (2*GSTAGE*2)        // 81920 bytes (also >= 128*129*4 epilogue tile)

__device__ __forceinline__ void gemm_mainloop(
        __nv_bfloat16* smg,
        const __nv_bfloat16* __restrict__ Ahi, const __nv_bfloat16* __restrict__ Alo,
        const __nv_bfloat16* __restrict__ Bhi, const __nv_bfloat16* __restrict__ Blo,
        int bm, int bn, int K, float acc[4][4][4],
        int tid, int wm, int wn, int lane) {
    const uint32_t sb = smem_u32(smg);
    const int cr0 = tid >> 2, cko0 = (tid & 3) << 3;
    const int cr1 = (tid + 256) >> 2, cko1 = ((tid + 256) & 3) << 3;

    uint32_t aoff[2];
    {
        int arow = (lane & 15), acol8 = (lane >> 4) << 3;
#pragma unroll
        for (int ks = 0; ks < 2; ks++)
            aoff[ks] = ((wm + arow) * SKP + ks * 16 + acol8) * 2;
    }
    // B-operand x4: lanes 0-7 -> rows nt (k0), 8-15 -> rows nt+1 (k0),
    // 16-23 -> rows nt (k8), 24-31 -> rows nt+1 (k8)
    uint32_t boff4;
    {
        int brow16 = ((lane >> 3) & 1) * 8 + (lane & 7);
        int bcol8  = (lane >> 4) << 3;
        boff4 = ((wn + brow16) * SKP + bcol8) * 2 + 2 * GBUF * 2;
    }

    const int nchunk = K >> 5;
    // prologue: stage chunk 0 into stage 0
    {
        const __nv_bfloat16* pAh = Ahi + (size_t)bm * K;
        const __nv_bfloat16* pAl = Alo + (size_t)bm * K;
        const __nv_bfloat16* pBh = Bhi + (size_t)bn * K;
        const __nv_bfloat16* pBl = Blo + (size_t)bn * K;
        uint32_t s0 = sb + (cr0 * SKP + cko0) * 2;
        uint32_t s1 = sb + (cr1 * SKP + cko1) * 2;
        size_t g0 = (size_t)cr0 * K + cko0;
        size_t g1 = (size_t)cr1 * K + cko1;
        cp_async16(s0,                pAh + g0);
        cp_async16(s0 + GBUF * 2,     pAl + g0);
        cp_async16(s0 + 2 * GBUF * 2, pBh + g0);
        cp_async16(s0 + 3 * GBUF * 2, pBl + g0);
        cp_async16(s1,                pAh + g1);
        cp_async16(s1 + GBUF * 2,     pAl + g1);
        cp_async16(s1 + 2 * GBUF * 2, pBh + g1);
        cp_async16(s1 + 3 * GBUF * 2, pBl + g1);
        CP_COMMIT();
    }

    for (int kc = 0; kc < nchunk; kc++) {
        const int cur = kc & 1;
        if (kc + 1 < nchunk) {
            const int nxt = cur ^ 1;
            const __nv_bfloat16* pAh = Ahi + (size_t)bm * K + (size_t)(kc + 1) * 32;
            const __nv_bfloat16* pAl = Alo + (size_t)bm * K + (size_t)(kc + 1) * 32;
            const __nv_bfloat16* pBh = Bhi + (size_t)bn * K + (size_t)(kc + 1) * 32;
            const __nv_bfloat16* pBl = Blo + (size_t)bn * K + (size_t)(kc + 1) * 32;
            uint32_t stb = sb + nxt * GSTAGE * 2;
            uint32_t s0 = stb + (cr0 * SKP + cko0) * 2;
            uint32_t s1 = stb + (cr1 * SKP + cko1) * 2;
            size_t g0 = (size_t)cr0 * K + cko0;
            size_t g1 = (size_t)cr1 * K + cko1;
            cp_async16(s0,                pAh + g0);
            cp_async16(s0 + GBUF * 2,     pAl + g0);
            cp_async16(s0 + 2 * GBUF * 2, pBh + g0);
            cp_async16(s0 + 3 * GBUF * 2, pBl + g0);
            cp_async16(s1,                pAh + g1);
            cp_async16(s1 + GBUF * 2,     pAl + g1);
            cp_async16(s1 + 2 * GBUF * 2, pBh + g1);
            cp_async16(s1 + 3 * GBUF * 2, pBl + g1);
            CP_COMMIT();
            CP_WAIT1();
        } else {
            CP_WAIT0();
        }
        __syncthreads();

        const uint32_t stg = sb + cur * GSTAGE * 2;
#pragma unroll
        for (int ks = 0; ks < 2; ks++) {
            uint32_t bh[4][2], bl[4][2];
#pragma unroll
            for (int pr = 0; pr < 2; pr++) {
                uint32_t th[4], tl[4];
                uint32_t bo = stg + boff4 + (uint32_t)(pr * 16 * SKP + ks * 16) * 2;
                ldsm_x4(th, bo);
                ldsm_x4(tl, bo + GBUF * 2);
                bh[pr * 2][0]     = th[0]; bh[pr * 2][1]     = th[2];
                bh[pr * 2 + 1][0] = th[1]; bh[pr * 2 + 1][1] = th[3];
                bl[pr * 2][0]     = tl[0]; bl[pr * 2][1]     = tl[2];
                bl[pr * 2 + 1][0] = tl[1]; bl[pr * 2 + 1][1] = tl[3];
            }
#pragma unroll
            for (int mt = 0; mt < 4; mt++) {
                uint32_t ah[4], al[4];
                ldsm_x4(ah, stg + aoff[ks] + mt * 16 * SKP * 2);
                ldsm_x4(al, stg + aoff[ks] + mt * 16 * SKP * 2 + GBUF * 2);
#pragma unroll
                for (int nt = 0; nt < 4; nt++) {
                    mma16816(acc[mt][nt], ah, bh[nt]);
                    mma16816(acc[mt][nt], ah, bl[nt]);
                    mma16816(acc[mt][nt], al, bh[nt]);
                }
            }
        }
        __syncthreads();
    }
}

// generic GEMM. EPI: 0 store fp32, 1 residual add, 3 gelu -> bf16 hi/lo split
template<int EPI>
__global__ __launch_bounds__(256, 2)
void hmma_gemm_kernel(const __nv_bfloat16* __restrict__ Ahi, const __nv_bfloat16* __restrict__ Alo,
                      const __nv_bfloat16* __restrict__ Bhi, const __nv_bfloat16* __restrict__ Blo,
                      const float* __restrict__ Cin, float* __restrict__ C,
                      __nv_bfloat16* __restrict__ Ghi, __nv_bfloat16* __restrict__ Glo,
                      int M, int N, int K) {
    extern __shared__ __nv_bfloat16 smg[];
    const int tid = threadIdx.x;
    const int bm = blockIdx.y * 128, bn = blockIdx.x * 128;
    const int w = tid >> 5, lane = tid & 31;
    const int wm = (w & 1) * 64, wn = (w >> 1) * 32;
    const int g = lane >> 2, tg = lane & 3;

    float acc[4][4][4] = {};
    gemm_mainloop(smg, Ahi, Alo, Bhi, Blo, bm, bn, K, acc, tid, wm, wn, lane);

#pragma unroll
    for (int mt = 0; mt < 4; mt++) {
        int row0 = bm + wm + mt * 16 + g;
        int row1 = row0 + 8;
#pragma unroll
        for (int nt = 0; nt < 4; nt++) {
            int col = bn + wn + nt * 8 + tg * 2;
            float c0 = acc[mt][nt][0], c1 = acc[mt][nt][1];
            float c2 = acc[mt][nt][2], c3 = acc[mt][nt][3];
            if (EPI == 0 || EPI == 1) {
                if (EPI == 1) {
                    float2 r0 = *(const float2*)(Cin + (size_t)row0 * N + col);
                    float2 r1 = *(const float2*)(Cin + (size_t)row1 * N + col);
                    c0 += r0.x; c1 += r0.y; c2 += r1.x; c3 += r1.y;
                }
                float2 v0 = {c0, c1}, v1 = {c2, c3};
                *(float2*)(C + (size_t)row0 * N + col) = v0;
                *(float2*)(C + (size_t)row1 * N + col) = v1;
            } else {
                float vv[4] = {c0, c1, c2, c3};
                __nv_bfloat16 h[4], l[4];
#pragma unroll
                for (int e = 0; e < 4; e++) {
                    float v = vv[e];
                    v = 0.5f * v * (1.0f + erff(v * 0.70710678118654752f));
                    h[e] = __float2bfloat16(v);
                    l[e] = __float2bfloat16(v - __bfloat162float(h[e]));
                }
                *(__nv_bfloat162*)(Ghi + (size_t)row0 * N + col) = {h[0], h[1]};
                *(__nv_bfloat162*)(Ghi + (size_t)row1 * N + col) = {h[2], h[3]};
                *(__nv_bfloat162*)(Glo + (size_t)row0 * N + col) = {l[0], l[1]};
                *(__nv_bfloat162*)(Glo + (size_t)row1 * N + col) = {l[2], l[3]};
            }
        }
    }
}

// fused QKV GEMM + rope/transpose epilogue.
// grid (12, 64); sel = blockIdx.x>>2 picks {Q,K,V}, (x&3) = 128-col n-block.
// Q/K: rope -> bf16 hi/lo in (B,H,S,Dh) (Q pre-scaled 1/8). V: transpose -> (B,H,Dh,S).
__global__ __launch_bounds__(256, 2)
void hmma_gemm_qkv(const __nv_bfloat16* __restrict__ Ahi, const __nv_bfloat16* __restrict__ Alo,
                   const __nv_bfloat16* __restrict__ WTh, const __nv_bfloat16* __restrict__ WTl,
                   __nv_bfloat16* __restrict__ Qoh, __nv_bfloat16* __restrict__ Qol,
                   __nv_bfloat16* __restrict__ Koh, __nv_bfloat16* __restrict__ Kol,
                   __nv_bfloat16* __restrict__ Voh, __nv_bfloat16* __restrict__ Vol,
                   const float* __restrict__ ct, const float* __restrict__ st) {
    extern __shared__ __nv_bfloat16 smg[];
    const int tid = threadIdx.x;
    const int sel = blockIdx.x >> 2;
    const int bm = blockIdx.y * 128, bn = (blockIdx.x & 3) * 128;
    const int w = tid >> 5, lane = tid & 31;
    const int wm = (w & 1) * 64, wn = (w >> 1) * 32;
    const int g = lane >> 2, tg = lane & 3;

    const __nv_bfloat16* Bhi = WTh + (size_t)sel * 512 * 512;
    const __nv_bfloat16* Blo = WTl + (size_t)sel * 512 * 512;

    float acc[4][4][4] = {};
    gemm_mainloop(smg, Ahi, Alo, Bhi, Blo, bm, bn, DIM, acc, tid, wm, wn, lane);

    // stage fp32 tile to smem (stride 129; mainloop ended on a bar, smem free)
    float* ft = (float*)smg;
#pragma unroll
    for (int mt = 0; mt < 4; mt++) {
        int r0 = wm + mt * 16 + g, r1 = r0 + 8;
#pragma unroll
        for (int nt = 0; nt < 4; nt++) {
            int c = wn + nt * 8 + tg * 2;
            ft[r0 * 129 + c]     = acc[mt][nt][0];
            ft[r0 * 129 + c + 1] = acc[mt][nt][1];
            ft[r1 * 129 + c]     = acc[mt][nt][2];
            ft[r1 * 129 + c + 1] = acc[mt][nt][3];
        }
    }
    __syncthreads();

    const int b  = bm >> 11;            // batch (128 | 2048 => tile within one batch)
    const int s0 = bm & (SEQ - 1);
    const int h0 = bn >> 6;             // first head in this 128-col block

    if (sel < 2) {
        const float scale = (sel == 0) ? 0.125f : 1.0f;
        __nv_bfloat16* oh = (sel == 0) ? Qoh : Koh;
        __nv_bfloat16* ol = (sel == 0) ? Qol : Kol;
#pragma unroll
        for (int k = 0; k < 32; k++) {
            int idx = tid + k * 256;            // 8192 pairs
            int i  = idx & 31;
            int lh = (idx >> 5) & 1;
            int r  = idx >> 6;
            int s  = s0 + r;
            float t1 = ft[r * 129 + lh * 64 + i];
            float t2 = ft[r * 129 + lh * 64 + i + 32];
            float c  = ct[s * 32 + i];
            float si = st[s * 32 + i];
            float y0 = (t1 * c - t2 * si) * scale;
            float y1 = (t1 * si + t2 * c) * scale;
            size_t base = (((size_t)(b * NH + h0 + lh)) * SEQ + s) * DHD;
            __nv_bfloat16 hh0 = __float2bfloat16(y0);
            __nv_bfloat16 hh1 = __float2bfloat16(y1);
            oh[base + i]      = hh0;
            ol[base + i]      = __float2bfloat16(y0 - __bfloat162float(hh0));
            oh[base + i + 32] = hh1;
            ol[base + i + 32] = __float2bfloat16(y1 - __bfloat162float(hh1));
        }
    } else {
#pragma unroll
        for (int k = 0; k < 64; k++) {
            int idx = tid + k * 256;            // 16384 elements
            int r = idx & 127;
            int c = idx >> 7;
            float v = ft[r * 129 + c];
            int d = c & 63, lh = c >> 6;
            size_t o = ((size_t)(b * NH + h0 + lh) * DHD + d) * SEQ + s0 + r;
            __nv_bfloat16 hh = __float2bfloat16(v);
            Voh[o] = hh;
            Vol[o] = __float2bfloat16(v - __bfloat162float(hh));
        }
    }
}

// ---------------- fused prep: rope table + all 12 weight transposes/splits ----------------
__global__ void prep_kernel(const float* __restrict__ Wq, const float* __restrict__ Wk,
                            const float* __restrict__ Wv, const float* __restrict__ Wo,
                            const float* __restrict__ W1, const float* __restrict__ W2,
                            __nv_bfloat16* __restrict__ Th, __nv_bfloat16* __restrict__ Tl,
                            float* __restrict__ ct, float* __restrict__ st) {
    int bid = blockIdx.x;
    if (bid < 256) {
        int i = threadIdx.x & 31;
        int s = bid * 8 + (threadIdx.x >> 5);
        double inv = pow(10000.0, -(double)i / 32.0);
        double ang = (double)s * inv;
        double sn, cs;
        sincos(ang, &sn, &cs);
        ct[s * 32 + i] = (float)cs;
        st[s * 32 + i] = (float)sn;
        return;
    }
    int idx = bid - 256;
    int l = idx / 3072;
    int r = idx % 3072;
    const float* W;
    int K, N, t;
    size_t doff;
    if (r < 1024) {
        int m = r >> 8; t = r & 255;
        const float* Ws4 = (m == 0) ? Wq : (m == 1) ? Wk : (m == 2) ? Wv : Wo;
        W = Ws4 + (size_t)l * DIM * DIM;
        K = 512; N = 512;
        doff = (size_t)l * WT_LAYER + (size_t)m * 512 * 512;
    } else if (r < 2048) {
        t = r - 1024;
        W = W1 + (size_t)l * DIM * FF;
        K = 512; N = 2048;
        doff = (size_t)l * WT_LAYER + WT_W1;
    } else {
        t = r - 2048;
        W = W2 + (size_t)l * FF * DIM;
        K = 2048; N = 512;
        doff = (size_t)l * WT_LAYER + WT_W2;
    }
    int ntiles = N >> 5;
    int bx = t % ntiles, by = t / ntiles;
    __shared__ float tile[32][33];
    int n0 = bx * 32, k0 = by * 32;
    int tx = threadIdx.x & 31, ty = threadIdx.x >> 5;
#pragma unroll
    for (int i = 0; i < 32; i += 8)
        tile[ty + i][tx] = W[(size_t)(k0 + ty + i) * N + n0 + tx];
    __syncthreads();
#pragma unroll
    for (int i = 0; i < 32; i += 8) {
        float v = tile[tx][ty + i];
        __nv_bfloat16 h = __float2bfloat16(v);
        __nv_bfloat16 lo = __float2bfloat16(v - __bfloat162float(h));
        size_t o = doff + (size_t)(n0 + ty + i) * K + k0 + tx;
        Th[o] = h; Tl[o] = lo;
    }
}

// ---------------- rmsnorm + bf16 hi/lo split ----------------
__global__ void rmsnorm_split_kernel(const float* __restrict__ x, const float* __restrict__ w,
                                     __nv_bfloat16* __restrict__ hi, __nv_bfloat16* __restrict__ lo) {
    int row = blockIdx.x;
    int t = threadIdx.x;
    const float* xr = x + (size_t)row * DIM;
    float v0 = xr[t], v1 = xr[t + 256];
    __shared__ float red[256];
    red[t] = v0 * v0 + v1 * v1;
    __syncthreads();
#pragma unroll
    for (int o = 128; o > 0; o >>= 1) {
        if (t < o) red[t] += red[t + o];
        __syncthreads();
    }
    float inv = rsqrtf(red[0] * (1.0f / (float)DIM) + 1e-6f);
    float y0 = v0 * inv * w[t];
    float y1 = v1 * inv * w[t + 256];
    __nv_bfloat16 h0 = __float2bfloat16(y0);
    __nv_bfloat16 h1 = __float2bfloat16(y1);
    size_t o0 = (size_t)row * DIM + t;
    hi[o0]       = h0;  lo[o0]       = __float2bfloat16(y0 - __bfloat162float(h0));
    hi[o0 + 256] = h1;  lo[o0 + 256] = __float2bfloat16(y1 - __bfloat162float(h1));
}

// ---------------- HMMA flash attention (exact R14-benched version) ----------------
#define AT_STR 72
#define FA_BUF (64*AT_STR)          // elements per operand buffer (4608)
#define FA_STAGE (4*FA_BUF)         // 18432 elements per stage
#define FA_QH_OFF (2*FA_STAGE)      // Q-hi element offset (36864)
#define FA_QBUF (128*AT_STR)        // 9216 elements per Q buffer
#define FA_SMEM ((2*FA_STAGE + 2*FA_QBUF) * 2)   // 110592 bytes

__global__ __launch_bounds__(256, 2)
void fa_kernel(const __nv_bfloat16* __restrict__ Qh, const __nv_bfloat16* __restrict__ Ql,
               const __nv_bfloat16* __restrict__ Kh, const __nv_bfloat16* __restrict__ Kl,
               const __nv_bfloat16* __restrict__ Vh, const __nv_bfloat16* __restrict__ Vl,
               __nv_bfloat16* __restrict__ Ohi, __nv_bfloat16* __restrict__ Olo) {
    extern __shared__ __nv_bfloat16 smb[];
    const uint32_t sbF = smem_u32(smb);

    const int bh = blockIdx.x;
    const int qt = (int)gridDim.y - 1 - (int)blockIdx.y;   // longest first
    const int tid = threadIdx.x, w = tid >> 5, lane = tid & 31;
    const int g = lane >> 2, tg = lane & 3;

    // ldmatrix per-lane offsets
    const uint32_t kboff = (((lane & 7) * AT_STR) + ((lane >> 3) << 3)) * 2;      // B operand
    const uint32_t qfoff = (uint32_t)(FA_QH_OFF + (w * 16 + (lane & 15)) * AT_STR
                                      + ((lane >> 4) << 3)) * 2;                  // A operand (Q)

    // ---- stage Q (128 rows hi + lo) into the dedicated Q region ----
    {
        const __nv_bfloat16* qbh = Qh + ((size_t)bh * SEQ + qt * 128) * DHD;
        const __nv_bfloat16* qbl = Ql + ((size_t)bh * SEQ + qt * 128) * DHD;
        for (int idx = tid; idx < 1024; idx += 256) {
            int r = idx >> 3, c = (idx & 7) << 3;
            *(uint4*)&smb[FA_QH_OFF + r * AT_STR + c]           = *(const uint4*)(qbh + r * DHD + c);
            *(uint4*)&smb[FA_QH_OFF + FA_QBUF + r * AT_STR + c] = *(const uint4*)(qbl + r * DHD + c);
        }
    }

    float accO[8][4] = {};
    float m0 = -1e30f, m1 = -1e30f, l0 = 0.f, l1 = 0.f;
    const int grow0 = qt * 128 + w * 16 + g;
    const int grow1 = grow0 + 8;

    const __nv_bfloat16* kbh = Kh + (size_t)bh * SEQ * DHD;
    const __nv_bfloat16* kbl = Kl + (size_t)bh * SEQ * DHD;
    const __nv_bfloat16* vbh = Vh + (size_t)bh * DHD * SEQ;
    const __nv_bfloat16* vbl = Vl + (size_t)bh * DHD * SEQ;

    const int ntiles = 2 * qt + 2;

    // prologue: stage tile 0 into stage 0
    {
        uint32_t stb = sbF;
        for (int i = 0; i < 2; i++) {
            int idx = tid + i * 256;
            int r = idx >> 3, c = (idx & 7) << 3;
            uint32_t so = stb + (r * AT_STR + c) * 2;
            cp_async16(so,                 kbh + (size_t)r * DHD + c);
            cp_async16(so + FA_BUF * 2,    kbl + (size_t)r * DHD + c);
            cp_async16(so + 2 * FA_BUF * 2, vbh + (size_t)r * SEQ + c);
            cp_async16(so + 3 * FA_BUF * 2, vbl + (size_t)r * SEQ + c);
        }
        CP_COMMIT();
    }

    for (int kt = 0; kt < ntiles; kt++) {
        const int cur = kt & 1;
        if (kt + 1 < ntiles) {
            uint32_t stb = sbF + (cur ^ 1) * FA_STAGE * 2;
            for (int i = 0; i < 2; i++) {
                int idx = tid + i * 256;
                int r = idx >> 3, c = (idx & 7) << 3;
                uint32_t so = stb + (r * AT_STR + c) * 2;
                cp_async16(so,                 kbh + (size_t)((kt + 1) * 64 + r) * DHD + c);
                cp_async16(so + FA_BUF * 2,    kbl + (size_t)((kt + 1) * 64 + r) * DHD + c);
                cp_async16(so + 2 * FA_BUF * 2, vbh + (size_t)r * SEQ + (kt + 1) * 64 + c);
                cp_async16(so + 3 * FA_BUF * 2, vbl + (size_t)r * SEQ + (kt + 1) * 64 + c);
            }
            CP_COMMIT();
            CP_WAIT1();
        } else {
            CP_WAIT0();
        }
        __syncthreads();   // also makes Q staging visible on first iteration

        const uint32_t sKhB = sbF + cur * FA_STAGE * 2;
        const uint32_t sKlB = sKhB + FA_BUF * 2;
        const uint32_t sVhB = sKhB + 2 * FA_BUF * 2;
        const uint32_t sVlB = sKhB + 3 * FA_BUF * 2;

        // S = Q @ K^T  (Q frags reloaded from smem; p-outer keeps only 16 Q regs live)
        float sc[8][4] = {};
#pragma unroll
        for (int p = 0; p < 2; p++) {
            uint32_t qh0[4], qh1[4], ql0[4], ql1[4];
            ldsm_x4(qh0, sbF + qfoff + p * 64);
            ldsm_x4(qh1, sbF + qfoff + p * 64 + 32);
            ldsm_x4(ql0, sbF + qfoff + FA_QBUF * 2 + p * 64);
            ldsm_x4(ql1, sbF + qfoff + FA_QBUF * 2 + p * 64 + 32);
#pragma unroll
            for (int nt = 0; nt < 8; nt++) {
                uint32_t rowb = (uint32_t)(nt * 8 * AT_STR * 2) + kboff;
                uint32_t bkh[4], bkl[4];
                ldsm_x4(bkh, sKhB + rowb + p * 64);
                ldsm_x4(bkl, sKlB + rowb + p * 64);
                mma16816(sc[nt], qh0, bkh);
                mma16816(sc[nt], qh0, bkl);
                mma16816(sc[nt], ql0, bkh);
                mma16816(sc[nt], qh1, bkh + 2);
                mma16816(sc[nt], qh1, bkl + 2);
                mma16816(sc[nt], ql1, bkh + 2);
            }
        }

        // causal mask on the last two tiles
        if (kt >= 2 * qt) {
#pragma unroll
            for (int nt = 0; nt < 8; nt++) {
                int keyg = kt * 64 + nt * 8 + tg * 2;
                if (keyg     > grow0) sc[nt][0] = -1e30f;
                if (keyg + 1 > grow0) sc[nt][1] = -1e30f;
                if (keyg     > grow1) sc[nt][2] = -1e30f;
                if (keyg + 1 > grow1) sc[nt][3] = -1e30f;
            }
        }

        // online softmax
        float mt0 = -1e30f, mt1 = -1e30f;
#pragma unroll
        for (int nt = 0; nt < 8; nt++) {
            mt0 = fmaxf(mt0, fmaxf(sc[nt][0], sc[nt][1]));
            mt1 = fmaxf(mt1, fmaxf(sc[nt][2], sc[nt][3]));
        }
        mt0 = fmaxf(mt0, __shfl_xor_sync(0xffffffffu, mt0, 1));
        mt0 = fmaxf(mt0, __shfl_xor_sync(0xffffffffu, mt0, 2));
        mt1 = fmaxf(mt1, __shfl_xor_sync(0xffffffffu, mt1, 1));
        mt1 = fmaxf(mt1, __shfl_xor_sync(0xffffffffu, mt1, 2));
        float mn0 = fmaxf(m0, mt0), mn1 = fmaxf(m1, mt1);
        float f0 = __expf(m0 - mn0), f1 = __expf(m1 - mn1);
        float s0 = 0.f, s1 = 0.f;
#pragma unroll
        for (int nt = 0; nt < 8; nt++) {
            float p0 = __expf(sc[nt][0] - mn0);
            float p1 = __expf(sc[nt][1] - mn0);
            float p2 = __expf(sc[nt][2] - mn1);
            float p3 = __expf(sc[nt][3] - mn1);
            sc[nt][0] = p0; sc[nt][1] = p1; sc[nt][2] = p2; sc[nt][3] = p3;
            s0 += p0 + p1; s1 += p2 + p3;
        }
        s0 += __shfl_xor_sync(0xffffffffu, s0, 1);
        s0 += __shfl_xor_sync(0xffffffffu, s0, 2);
        s1 += __shfl_xor_sync(0xffffffffu, s1, 1);
        s1 += __shfl_xor_sync(0xffffffffu, s1, 2);
        l0 = l0 * f0 + s0;
        l1 = l1 * f1 + s1;
        m0 = mn0; m1 = mn1;
#pragma unroll
        for (int dt = 0; dt < 8; dt++) {
            accO[dt][0] *= f0; accO[dt][1] *= f0;
            accO[dt][2] *= f1; accO[dt][3] *= f1;
        }

        // O += P @ V (P re-split hi/lo in registers; ldsm_x4 covers two k16 frags)
#pragma unroll
        for (int jp = 0; jp < 2; jp++) {
            uint32_t aPh[2][4], aPl[2][4];
#pragma unroll
            for (int jj = 0; jj < 2; jj++) {
                int j = jp * 2 + jj;
                float x00 = sc[2*j][0],   x01 = sc[2*j][1],   x02 = sc[2*j][2],   x03 = sc[2*j][3];
                float x10 = sc[2*j+1][0], x11 = sc[2*j+1][1], x12 = sc[2*j+1][2], x13 = sc[2*j+1][3];
                aPh[jj][0] = pack_bf16x2(x00, x01);
                aPh[jj][1] = pack_bf16x2(x02, x03);
                aPh[jj][2] = pack_bf16x2(x10, x11);
                aPh[jj][3] = pack_bf16x2(x12, x13);
                __nv_bfloat162* t;
                t = (__nv_bfloat162*)&aPh[jj][0];
                aPl[jj][0] = pack_bf16x2(x00 - __bfloat162float(t->x), x01 - __bfloat162float(t->y));
                t = (__nv_bfloat162*)&aPh[jj][1];
                aPl[jj][1] = pack_bf16x2(x02 - __bfloat162float(t->x), x03 - __bfloat162float(t->y));
                t = (__nv_bfloat162*)&aPh[jj][2];
                aPl[jj][2] = pack_bf16x2(x10 - __bfloat162float(t->x), x11 - __bfloat162float(t->y));
                t = (__nv_bfloat162*)&aPh[jj][3];
                aPl[jj][3] = pack_bf16x2(x12 - __bfloat162float(t->x), x13 - __bfloat162float(t->y));
            }
#pragma unroll
            for (int dt = 0; dt < 8; dt++) {
                uint32_t rb = (uint32_t)(dt * 8 * AT_STR * 2) + kboff + jp * 64;
                uint32_t bvh[4], bvl[4];
                ldsm_x4(bvh, sVhB + rb);
                ldsm_x4(bvl, sVlB + rb);
                mma16816(accO[dt], aPh[0], bvh);
                mma16816(accO[dt], aPh[0], bvl);
                mma16816(accO[dt], aPl[0], bvh);
                mma16816(accO[dt], aPh[1], bvh + 2);
                mma16816(accO[dt], aPh[1], bvl + 2);
                mma16816(accO[dt], aPl[1], bvh + 2);
            }
        }
        __syncthreads();
    }

    // epilogue -> (B,S,D) bf16 hi/lo
    float il0 = 1.0f / l0, il1 = 1.0f / l1;
    int b = bh >> 3, h = bh & 7;
    size_t row0 = (size_t)b * SEQ + qt * 128 + w * 16 + g;
    size_t row1 = row0 + 8;
#pragma unroll
    for (int dt = 0; dt < 8; dt++) {
        int col = h * DHD + dt * 8 + tg * 2;
        float o0 = accO[dt][0] * il0, o1 = accO[dt][1] * il0;
        float o2 = accO[dt][2] * il1, o3 = accO[dt][3] * il1;
        __nv_bfloat16 h0 = __float2bfloat16(o0), h1 = __float2bfloat16(o1);
        __nv_bfloat16 h2 = __float2bfloat16(o2), h3 = __float2bfloat16(o3);
        *(__nv_bfloat162*)(Ohi + row0 * DIM + col) = {h0, h1};
        *(__nv_bfloat162*)(Ohi + row1 * DIM + col) = {h2, h3};
        *(__nv_bfloat162*)(Olo + row0 * DIM + col) =
            {__float2bfloat16(o0 - __bfloat162float(h0)), __float2bfloat16(o1 - __bfloat162float(h1))};
        *(__nv_bfloat162*)(Olo + row1 * DIM + col) =
            {__float2bfloat16(o2 - __bfloat162float(h2)), __float2bfloat16(o3 - __bfloat162float(h3))};
    }
}

// ---------------- head: logits -> sigmoid probs ----------------
__global__ void head_kernel(const float* __restrict__ X, const float* __restrict__ hw,
                            const float* __restrict__ hb, float* __restrict__ probs) {
    int row = blockIdx.x * 8 + (threadIdx.x >> 5);
    int lane = threadIdx.x & 31;
    const float* xr = X + (size_t)row * DIM;
    float s = 0.f;
    for (int i = lane; i < DIM; i += 32) s = fmaf(xr[i], hw[i], s);
#pragma unroll
    for (int o = 16; o; o >>= 1) s += __shfl_xor_sync(0xffffffffu, s, o);
    if (lane == 0) {
        float logit = s + hb[0];
        probs[row] = 1.0f / (1.0f + expf(-logit));
    }
}

// ---------------- chunking (serial boundaries in smem, parallel id fill) ----------------
__global__ void chunk_kernel(const float* __restrict__ probs, int* __restrict__ ids,
                             int* __restrict__ nch, float* __restrict__ psum) {
    int b = blockIdx.x, t = threadIdx.x;
    __shared__ int flags[SEQ];
    __shared__ int ids_s[SEQ];
    __shared__ float red[256];
    const float* pr = probs + (size_t)b * SEQ;
    float s = 0.f; int any = 0;
    for (int i = t; i < SEQ; i += 256) {
        float p = pr[i];
        int f = (p > 0.5f) ? 1 : 0;
        flags[i] = f; s += p; any |= f;
    }
    red[t] = s;
    __syncthreads();
#pragma unroll
    for (int o = 128; o > 0; o >>= 1) {
        if (t < o) red[t] += red[t + o];
        __syncthreads();
    }
    int anyflag = __syncthreads_or(any);
    if (t == 0) {
        psum[b] = red[0];
        int cur_end = 0, cid = -1;
        for (int tt = 0; tt < SEQ; tt++) {
            if (tt == cur_end) {
                int cap = tt + 16; if (cap > SEQ) cap = SEQ;
                int e = cap;
                for (int ss = tt + 1; ss <= cap; ss++) {
                    int he = anyflag ? flags[ss - 1] : (ss == SEQ - 1);
                    if (he) { e = ss; break; }
                }
                if (e - tt < 3) { e = tt + 3; if (e > SEQ) e = SEQ; }
                cur_end = e; cid++;
            }
            ids_s[tt] = cid;
        }
        nch[b] = cid + 1;
    }
    __syncthreads();
    for (int i = t; i < SEQ; i += 256) ids[b * SEQ + i] = ids_s[i];
}

// ---------------- mask ----------------
__global__ void mask_kernel(const int* __restrict__ ids, float* __restrict__ out) {
    int i4 = blockIdx.x * 256 + threadIdx.x;
    int j = (i4 & 511) << 2;
    int rowIdx = i4 >> 9;
    int b = rowIdx >> 11;
    int idi = ids[rowIdx];
    const int* idr = ids + b * SEQ;
    size_t base = ((size_t)rowIdx << 11) + j;
    out[base + 0] = (idi == idr[j + 0]) ? 1.f : 0.f;
    out[base + 1] = (idi == idr[j + 1]) ? 1.f : 0.f;
    out[base + 2] = (idi == idr[j + 2]) ? 1.f : 0.f;
    out[base + 3] = (idi == idr[j + 3]) ? 1.f : 0.f;
}

__global__ void scalars_kernel(const int* __restrict__ nch, const float* __restrict__ psum,
                               float* __restrict__ out_acl, float* __restrict__ out_cll) {
    float a = 0.f, c = 0.f;
    for (int b = 0; b < NUM_B; b++) {
        a += (float)SEQ / (float)nch[b];
        c += psum[b];
    }
    *out_acl = a * 0.25f;
    *out_cll = c * 0.25f;
}

__global__ void xids_kernel(const int* __restrict__ xids, float* __restrict__ out) {
    int i = blockIdx.x * 256 + threadIdx.x;
    out[i] = (float)xids[i];
}

// ---------------- launch ----------------
extern "C" void kernel_launch(void* const* d_in, const int* in_sizes, int n_in,
                              void* d_out, int out_size) {
    const float* x    = (const float*)d_in[0];
    const int*   xids = (const int*)  d_in[1];
    const float* ln1  = (const float*)d_in[2];
    const float* Wq   = (const float*)d_in[3];
    const float* Wk   = (const float*)d_in[4];
    const float* Wv   = (const float*)d_in[5];
    const float* Wo   = (const float*)d_in[6];
    const float* ln2  = (const float*)d_in[7];
    const float* W1   = (const float*)d_in[8];
    const float* W2   = (const float*)d_in[9];
    const float* hw   = (const float*)d_in[10];
    const float* hb   = (const float*)d_in[11];
    float* out = (float*)d_out;

    float *X, *probs, *psum, *rc, *rs;
    __nv_bfloat16 *Ahi, *Alo, *Ghi, *Glo, *WThi, *WTlo;
    __nv_bfloat16 *Qbh, *Qbl, *Kbh, *Kbl, *Vbh, *Vbl;
    int *ids, *nch;
    cudaGetSymbolAddress((void**)&X,  g_X);
    cudaGetSymbolAddress((void**)&Qbh, g_Qbh);
    cudaGetSymbolAddress((void**)&Qbl, g_Qbl);
    cudaGetSymbolAddress((void**)&Kbh, g_Kbh);
    cudaGetSymbolAddress((void**)&Kbl, g_Kbl);
    cudaGetSymbolAddress((void**)&Vbh, g_Vbh);
    cudaGetSymbolAddress((void**)&Vbl, g_Vbl);
    cudaGetSymbolAddress((void**)&Ahi, g_Ahi);
    cudaGetSymbolAddress((void**)&Alo, g_Alo);
    cudaGetSymbolAddress((void**)&Ghi, g_Ghi);
    cudaGetSymbolAddress((void**)&Glo, g_Glo);
    cudaGetSymbolAddress((void**)&WThi, g_WThi);
    cudaGetSymbolAddress((void**)&WTlo, g_WTlo);
    cudaGetSymbolAddress((void**)&probs, g_probs);
    cudaGetSymbolAddress((void**)&psum,  g_psum);
    cudaGetSymbolAddress((void**)&ids, g_ids);
    cudaGetSymbolAddress((void**)&nch, g_nch);
    cudaGetSymbolAddress((void**)&rc, g_rc);
    cudaGetSymbolAddress((void**)&rs, g_rs);

    cudaFuncSetAttribute(hmma_gemm_kernel<1>, cudaFuncAttributeMaxDynamicSharedMemorySize, GM_SMEM2);
    cudaFuncSetAttribute(hmma_gemm_kernel<3>, cudaFuncAttributeMaxDynamicSharedMemorySize, GM_SMEM2);
    cudaFuncSetAttribute(hmma_gemm_qkv, cudaFuncAttributeMaxDynamicSharedMemorySize, GM_SMEM2);
    cudaFuncSetAttribute(fa_kernel, cudaFuncAttributeMaxDynamicSharedMemorySize, FA_SMEM);

    // fused prep: rope table + all weight transposes/splits in one launch
    prep_kernel<<<256 + NLAYER * 3072, 256>>>(Wq, Wk, Wv, Wo, W1, W2, WThi, WTlo, rc, rs);
    cudaMemcpyAsync(X, x, sizeof(float) * (size_t)ROWS * DIM, cudaMemcpyDeviceToDevice, 0);

    dim3 g512(DIM / 128, ROWS / 128);   // (4, 64)
    dim3 gqkv(12, ROWS / 128);          // fused QKV: 3 x 4 n-blocks
    dim3 gff (FF  / 128, ROWS / 128);   // (16, 64)
    dim3 gfa (NUM_B * NH, SEQ / 128);   // bh fastest, qt reversed inside

    for (int l = 0; l < NLAYER; l++) {
        const __nv_bfloat16* th = WThi + (size_t)l * WT_LAYER;
        const __nv_bfloat16* tl = WTlo + (size_t)l * WT_LAYER;

        rmsnorm_split_kernel<<<ROWS, 256>>>(X, ln1 + l * DIM, Ahi, Alo);
        hmma_gemm_qkv<<<gqkv, 256, GM_SMEM2>>>(Ahi, Alo, th, tl,
                                               Qbh, Qbl, Kbh, Kbl, Vbh, Vbl, rc, rs);
        fa_kernel<<<gfa, 256, FA_SMEM>>>(Qbh, Qbl, Kbh, Kbl, Vbh, Vbl, Ahi, Alo);
        hmma_gemm_kernel<1><<<g512, 256, GM_SMEM2>>>(Ahi, Alo, th + WT_O, tl + WT_O,
                                                     X, X, nullptr, nullptr, ROWS, DIM, DIM);
        rmsnorm_split_kernel<<<ROWS, 256>>>(X, ln2 + l * DIM, Ahi, Alo);
        hmma_gemm_kernel<3><<<gff, 256, GM_SMEM2>>>(Ahi, Alo, th + WT_W1, tl + WT_W1,
                                                    nullptr, nullptr, Ghi, Glo, ROWS, FF, DIM);
        hmma_gemm_kernel<1><<<g512, 256, GM_SMEM2>>>(Ghi, Glo, th + WT_W2, tl + WT_W2,
                                                     X, X, nullptr, nullptr, ROWS, DIM, FF);
    }

    head_kernel <<<ROWS / 8, 256>>>(X, hw, hb, probs);
    chunk_kernel<<<NUM_B, 256>>>(probs, ids, nch, psum);
    mask_kernel <<<(N_MASK / 4) / 256, 256>>>(ids, out + OFF_MASK);
    scalars_kernel<<<1, 1>>>(nch, psum, out + OFF_ACL, out + OFF_CLL);
    xids_kernel <<<ROWS / 256, 256>>>(xids, out + OFF_IDS);
    cudaMemcpyAsync(out + OFF_XT, X, sizeof(float) * (size_t)ROWS * DIM, cudaMemcpyDeviceToDevice, 0);
}

// round 16
// speedup vs baseline: 1.0768x; 1.0768x over previous
#include <cuda_runtime.h>
#include <cuda_bf16.h>
#include <math.h>
#include <stdint.h>
#include <stddef.h>

// ---------------- problem constants ----------------
#define NUM_B 4
#define SEQ   2048
#define DIM   512
#define NH    8
#define DHD   64
#define FF    2048
#define ROWS  (NUM_B*SEQ)          // 8192
#define NLAYER 2

// output layout (float32, concatenated in reference return order)
#define OFF_XT   0
#define N_XT     (ROWS*DIM)                 // 4194304
#define OFF_IDS  (OFF_XT + N_XT)            // 4194304
#define N_IDS    (ROWS)                     // 8192
#define OFF_ACL  (OFF_IDS + N_IDS)          // 4202496
#define OFF_MASK (OFF_ACL + 1)              // 4202497 (odd -> scalar stores only)
#define N_MASK   (NUM_B*SEQ*SEQ)            // 16777216
#define OFF_CLL  (OFF_MASK + N_MASK)        // 20979713

// per-layer transposed-weight bf16 buffer layout (elements)
#define WT_Q   0
#define WT_K   (512*512)
#define WT_V   (2*512*512)
#define WT_O   (3*512*512)
#define WT_W1  (4*512*512)                  // [2048][512]
#define WT_W2  (4*512*512 + 2048*512)       // [512][2048]
#define WT_LAYER (4*512*512 + 2*2048*512)   // 3145728

// ---------------- scratch (device globals; no allocation allowed) ----------------
__device__ float g_X [ROWS*DIM];
__device__ __nv_bfloat16 g_Qbh[ROWS*DIM];   // (B,H,S,Dh) hi, pre-scaled 1/8
__device__ __nv_bfloat16 g_Qbl[ROWS*DIM];
__device__ __nv_bfloat16 g_Kbh[ROWS*DIM];   // (B,H,S,Dh)
__device__ __nv_bfloat16 g_Kbl[ROWS*DIM];
__device__ __nv_bfloat16 g_Vbh[ROWS*DIM];   // (B,H,Dh,S)
__device__ __nv_bfloat16 g_Vbl[ROWS*DIM];
__device__ __nv_bfloat16 g_Ahi[ROWS*DIM];
__device__ __nv_bfloat16 g_Alo[ROWS*DIM];
__device__ __nv_bfloat16 g_Ghi[ROWS*FF];
__device__ __nv_bfloat16 g_Glo[ROWS*FF];
__device__ __nv_bfloat16 g_WThi[NLAYER*WT_LAYER];
__device__ __nv_bfloat16 g_WTlo[NLAYER*WT_LAYER];
__device__ float g_probs[ROWS];
__device__ int   g_ids[ROWS];
__device__ int   g_nch[NUM_B];
__device__ float g_psum[NUM_B];
__device__ float g_rc[SEQ*32];
__device__ float g_rs[SEQ*32];

// ---------------- low-level helpers ----------------
__device__ __forceinline__ void mma16816(float* c, const uint32_t* a, const uint32_t* b) {
    asm volatile(
        "mma.sync.aligned.m16n8k16.row.col.f32.bf16.bf16.f32 "
        "{%0,%1,%2,%3}, {%4,%5,%6,%7}, {%8,%9}, {%0,%1,%2,%3};"
        : "+f"(c[0]), "+f"(c[1]), "+f"(c[2]), "+f"(c[3])
        : "r"(a[0]), "r"(a[1]), "r"(a[2]), "r"(a[3]), "r"(b[0]), "r"(b[1]));
}

__device__ __forceinline__ uint32_t pack_bf16x2(float x, float y) {
    __nv_bfloat162 t;
    t.x = __float2bfloat16(x);
    t.y = __float2bfloat16(y);
    return *(uint32_t*)&t;
}

__device__ __forceinline__ uint32_t smem_u32(const void* p) {
    uint32_t a;
    asm("{ .reg .u64 t; cvta.to.shared.u64 t, %1; cvt.u32.u64 %0, t; }" : "=r"(a) : "l"(p));
    return a;
}

__device__ __forceinline__ void cp_async16(uint32_t saddr, const void* gaddr) {
    asm volatile("cp.async.ca.shared.global [%0], [%1], 16;" :: "r"(saddr), "l"(gaddr));
}
#define CP_COMMIT() asm volatile("cp.async.commit_group;" ::: "memory")
#define CP_WAIT1()  asm volatile("cp.async.wait_group 1;" ::: "memory")
#define CP_WAIT0()  asm volatile("cp.async.wait_group 0;" ::: "memory")

__device__ __forceinline__ void ldsm_x4(uint32_t* r, uint32_t saddr) {
    asm volatile("ldmatrix.sync.aligned.m8n8.x4.shared.b16 {%0,%1,%2,%3}, [%4];"
        : "=r"(r[0]), "=r"(r[1]), "=r"(r[2]), "=r"(r[3]) : "r"(saddr));
}
__device__ __forceinline__ void ldsm_x2(uint32_t* r, uint32_t saddr) {
    asm volatile("ldmatrix.sync.aligned.m8n8.x2.shared.b16 {%0,%1}, [%2];"
        : "=r"(r[0]), "=r"(r[1]) : "r"(saddr));
}

// ---------------- GEMM mainloop (exact R14-benched version: ldsm_x2 B) -------
#define SKP 40                       // padded smem row stride (elements); 80B
#define GBUF (128*SKP)               // elements per operand buffer
#define GSTAGE (4*GBUF)              // elements per stage (Ah,Al,Bh,Bl)
#define GM_SMEM2 (2*GSTAGE*2)        // 81920 bytes (also >= 128*129*4 epilogue tile)

__device__ __forceinline__ void gemm_mainloop(
        __nv_bfloat16* smg,
        const __nv_bfloat16* __restrict__ Ahi, const __nv_bfloat16* __restrict__ Alo,
        const __nv_bfloat16* __restrict__ Bhi, const __nv_bfloat16* __restrict__ Blo,
        int bm, int bn, int K, float acc[4][4][4],
        int tid, int wm, int wn, int lane) {
    const uint32_t sb = smem_u32(smg);
    const int cr0 = tid >> 2, cko0 = (tid & 3) << 3;
    const int cr1 = (tid + 256) >> 2, cko1 = ((tid + 256) & 3) << 3;

    uint32_t aoff[2], boff[2];
    {
        int arow = (lane & 15), acol8 = (lane >> 4) << 3;
        int lb = lane & 15;
        int brow = (lb & 7), bcol8 = (lb >> 3) << 3;
#pragma unroll
        for (int ks = 0; ks < 2; ks++) {
            aoff[ks] = ((wm + arow) * SKP + ks * 16 + acol8) * 2;
            boff[ks] = ((wn + brow) * SKP + ks * 16 + bcol8) * 2 + 2 * GBUF * 2;
        }
    }

    const int nchunk = K >> 5;
    // prologue: stage chunk 0 into stage 0
    {
        const __nv_bfloat16* pAh = Ahi + (size_t)bm * K;
        const __nv_bfloat16* pAl = Alo + (size_t)bm * K;
        const __nv_bfloat16* pBh = Bhi + (size_t)bn * K;
        const __nv_bfloat16* pBl = Blo + (size_t)bn * K;
        uint32_t s0 = sb + (cr0 * SKP + cko0) * 2;
        uint32_t s1 = sb + (cr1 * SKP + cko1) * 2;
        size_t g0 = (size_t)cr0 * K + cko0;
        size_t g1 = (size_t)cr1 * K + cko1;
        cp_async16(s0,                pAh + g0);
        cp_async16(s0 + GBUF * 2,     pAl + g0);
        cp_async16(s0 + 2 * GBUF * 2, pBh + g0);
        cp_async16(s0 + 3 * GBUF * 2, pBl + g0);
        cp_async16(s1,                pAh + g1);
        cp_async16(s1 + GBUF * 2,     pAl + g1);
        cp_async16(s1 + 2 * GBUF * 2, pBh + g1);
        cp_async16(s1 + 3 * GBUF * 2, pBl + g1);
        CP_COMMIT();
    }

    for (int kc = 0; kc < nchunk; kc++) {
        const int cur = kc & 1;
        if (kc + 1 < nchunk) {
            const int nxt = cur ^ 1;
            const __nv_bfloat16* pAh = Ahi + (size_t)bm * K + (size_t)(kc + 1) * 32;
            const __nv_bfloat16* pAl = Alo + (size_t)bm * K + (size_t)(kc + 1) * 32;
            const __nv_bfloat16* pBh = Bhi + (size_t)bn * K + (size_t)(kc + 1) * 32;
            const __nv_bfloat16* pBl = Blo + (size_t)bn * K + (size_t)(kc + 1) * 32;
            uint32_t stb = sb + nxt * GSTAGE * 2;
            uint32_t s0 = stb + (cr0 * SKP + cko0) * 2;
            uint32_t s1 = stb + (cr1 * SKP + cko1) * 2;
            size_t g0 = (size_t)cr0 * K + cko0;
            size_t g1 = (size_t)cr1 * K + cko1;
            cp_async16(s0,                pAh + g0);
            cp_async16(s0 + GBUF * 2,     pAl + g0);
            cp_async16(s0 + 2 * GBUF * 2, pBh + g0);
            cp_async16(s0 + 3 * GBUF * 2, pBl + g0);
            cp_async16(s1,                pAh + g1);
            cp_async16(s1 + GBUF * 2,     pAl + g1);
            cp_async16(s1 + 2 * GBUF * 2, pBh + g1);
            cp_async16(s1 + 3 * GBUF * 2, pBl + g1);
            CP_COMMIT();
            CP_WAIT1();
        } else {
            CP_WAIT0();
        }
        __syncthreads();

        const uint32_t stg = sb + cur * GSTAGE * 2;
#pragma unroll
        for (int ks = 0; ks < 2; ks++) {
            uint32_t bh[4][2], bl[4][2];
#pragma unroll
            for (int nt = 0; nt < 4; nt++) {
                ldsm_x2(bh[nt], stg + boff[ks] + nt * 8 * SKP * 2);
                ldsm_x2(bl[nt], stg + boff[ks] + nt * 8 * SKP * 2 + GBUF * 2);
            }
#pragma unroll
            for (int mt = 0; mt < 4; mt++) {
                uint32_t ah[4], al[4];
                ldsm_x4(ah, stg + aoff[ks] + mt * 16 * SKP * 2);
                ldsm_x4(al, stg + aoff[ks] + mt * 16 * SKP * 2 + GBUF * 2);
#pragma unroll
                for (int nt = 0; nt < 4; nt++) {
                    mma16816(acc[mt][nt], ah, bh[nt]);
                    mma16816(acc[mt][nt], ah, bl[nt]);
                    mma16816(acc[mt][nt], al, bh[nt]);
                }
            }
        }
        __syncthreads();
    }
}

// generic GEMM. EPI: 0 store fp32, 1 residual add, 3 gelu -> bf16 hi/lo split
template<int EPI>
__global__ __launch_bounds__(256, 2)
void hmma_gemm_kernel(const __nv_bfloat16* __restrict__ Ahi, const __nv_bfloat16* __restrict__ Alo,
                      const __nv_bfloat16* __restrict__ Bhi, const __nv_bfloat16* __restrict__ Blo,
                      const float* __restrict__ Cin, float* __restrict__ C,
                      __nv_bfloat16* __restrict__ Ghi, __nv_bfloat16* __restrict__ Glo,
                      int M, int N, int K) {
    extern __shared__ __nv_bfloat16 smg[];
    const int tid = threadIdx.x;
    const int bm = blockIdx.y * 128, bn = blockIdx.x * 128;
    const int w = tid >> 5, lane = tid & 31;
    const int wm = (w & 1) * 64, wn = (w >> 1) * 32;
    const int g = lane >> 2, tg = lane & 3;

    float acc[4][4][4] = {};
    gemm_mainloop(smg, Ahi, Alo, Bhi, Blo, bm, bn, K, acc, tid, wm, wn, lane);

#pragma unroll
    for (int mt = 0; mt < 4; mt++) {
        int row0 = bm + wm + mt * 16 + g;
        int row1 = row0 + 8;
#pragma unroll
        for (int nt = 0; nt < 4; nt++) {
            int col = bn + wn + nt * 8 + tg * 2;
            float c0 = acc[mt][nt][0], c1 = acc[mt][nt][1];
            float c2 = acc[mt][nt][2], c3 = acc[mt][nt][3];
            if (EPI == 0 || EPI == 1) {
                if (EPI == 1) {
                    float2 r0 = *(const float2*)(Cin + (size_t)row0 * N + col);
                    float2 r1 = *(const float2*)(Cin + (size_t)row1 * N + col);
                    c0 += r0.x; c1 += r0.y; c2 += r1.x; c3 += r1.y;
                }
                float2 v0 = {c0, c1}, v1 = {c2, c3};
                *(float2*)(C + (size_t)row0 * N + col) = v0;
                *(float2*)(C + (size_t)row1 * N + col) = v1;
            } else {
                float vv[4] = {c0, c1, c2, c3};
                __nv_bfloat16 h[4], l[4];
#pragma unroll
                for (int e = 0; e < 4; e++) {
                    float v = vv[e];
                    v = 0.5f * v * (1.0f + erff(v * 0.70710678118654752f));
                    h[e] = __float2bfloat16(v);
                    l[e] = __float2bfloat16(v - __bfloat162float(h[e]));
                }
                *(__nv_bfloat162*)(Ghi + (size_t)row0 * N + col) = {h[0], h[1]};
                *(__nv_bfloat162*)(Ghi + (size_t)row1 * N + col) = {h[2], h[3]};
                *(__nv_bfloat162*)(Glo + (size_t)row0 * N + col) = {l[0], l[1]};
                *(__nv_bfloat162*)(Glo + (size_t)row1 * N + col) = {l[2], l[3]};
            }
        }
    }
}

// fused QKV GEMM + rope/transpose epilogue.
// grid (12, 64); sel = blockIdx.x>>2 picks {Q,K,V}, (x&3) = 128-col n-block.
// Q/K: rope -> bf16 hi/lo in (B,H,S,Dh) (Q pre-scaled 1/8). V: transpose -> (B,H,Dh,S).
__global__ __launch_bounds__(256, 2)
void hmma_gemm_qkv(const __nv_bfloat16* __restrict__ Ahi, const __nv_bfloat16* __restrict__ Alo,
                   const __nv_bfloat16* __restrict__ WTh, const __nv_bfloat16* __restrict__ WTl,
                   __nv_bfloat16* __restrict__ Qoh, __nv_bfloat16* __restrict__ Qol,
                   __nv_bfloat16* __restrict__ Koh, __nv_bfloat16* __restrict__ Kol,
                   __nv_bfloat16* __restrict__ Voh, __nv_bfloat16* __restrict__ Vol,
                   const float* __restrict__ ct, const float* __restrict__ st) {
    extern __shared__ __nv_bfloat16 smg[];
    const int tid = threadIdx.x;
    const int sel = blockIdx.x >> 2;
    const int bm = blockIdx.y * 128, bn = (blockIdx.x & 3) * 128;
    const int w = tid >> 5, lane = tid & 31;
    const int wm = (w & 1) * 64, wn = (w >> 1) * 32;
    const int g = lane >> 2, tg = lane & 3;

    const __nv_bfloat16* Bhi = WTh + (size_t)sel * 512 * 512;
    const __nv_bfloat16* Blo = WTl + (size_t)sel * 512 * 512;

    float acc[4][4][4] = {};
    gemm_mainloop(smg, Ahi, Alo, Bhi, Blo, bm, bn, DIM, acc, tid, wm, wn, lane);

    // stage fp32 tile to smem (stride 129; mainloop ended on a bar, smem free)
    float* ft = (float*)smg;
#pragma unroll
    for (int mt = 0; mt < 4; mt++) {
        int r0 = wm + mt * 16 + g, r1 = r0 + 8;
#pragma unroll
        for (int nt = 0; nt < 4; nt++) {
            int c = wn + nt * 8 + tg * 2;
            ft[r0 * 129 + c]     = acc[mt][nt][0];
            ft[r0 * 129 + c + 1] = acc[mt][nt][1];
            ft[r1 * 129 + c]     = acc[mt][nt][2];
            ft[r1 * 129 + c + 1] = acc[mt][nt][3];
        }
    }
    __syncthreads();

    const int b  = bm >> 11;            // batch (128 | 2048 => tile within one batch)
    const int s0 = bm & (SEQ - 1);
    const int h0 = bn >> 6;             // first head in this 128-col block

    if (sel < 2) {
        const float scale = (sel == 0) ? 0.125f : 1.0f;
        __nv_bfloat16* oh = (sel == 0) ? Qoh : Koh;
        __nv_bfloat16* ol = (sel == 0) ? Qol : Kol;
#pragma unroll
        for (int k = 0; k < 32; k++) {
            int idx = tid + k * 256;            // 8192 pairs
            int i  = idx & 31;
            int lh = (idx >> 5) & 1;
            int r  = idx >> 6;
            int s  = s0 + r;
            float t1 = ft[r * 129 + lh * 64 + i];
            float t2 = ft[r * 129 + lh * 64 + i + 32];
            float c  = ct[s * 32 + i];
            float si = st[s * 32 + i];
            float y0 = (t1 * c - t2 * si) * scale;
            float y1 = (t1 * si + t2 * c) * scale;
            size_t base = (((size_t)(b * NH + h0 + lh)) * SEQ + s) * DHD;
            __nv_bfloat16 hh0 = __float2bfloat16(y0);
            __nv_bfloat16 hh1 = __float2bfloat16(y1);
            oh[base + i]      = hh0;
            ol[base + i]      = __float2bfloat16(y0 - __bfloat162float(hh0));
            oh[base + i + 32] = hh1;
            ol[base + i + 32] = __float2bfloat16(y1 - __bfloat162float(hh1));
        }
    } else {
#pragma unroll
        for (int k = 0; k < 64; k++) {
            int idx = tid + k * 256;            // 16384 elements
            int r = idx & 127;
            int c = idx >> 7;
            float v = ft[r * 129 + c];
            int d = c & 63, lh = c >> 6;
            size_t o = ((size_t)(b * NH + h0 + lh) * DHD + d) * SEQ + s0 + r;
            __nv_bfloat16 hh = __float2bfloat16(v);
            Voh[o] = hh;
            Vol[o] = __float2bfloat16(v - __bfloat162float(hh));
        }
    }
}

// ---------------- fused prep: rope table + all 12 weight transposes/splits ----------------
__global__ void prep_kernel(const float* __restrict__ Wq, const float* __restrict__ Wk,
                            const float* __restrict__ Wv, const float* __restrict__ Wo,
                            const float* __restrict__ W1, const float* __restrict__ W2,
                            __nv_bfloat16* __restrict__ Th, __nv_bfloat16* __restrict__ Tl,
                            float* __restrict__ ct, float* __restrict__ st) {
    int bid = blockIdx.x;
    if (bid < 256) {
        int i = threadIdx.x & 31;
        int s = bid * 8 + (threadIdx.x >> 5);
        double inv = pow(10000.0, -(double)i / 32.0);
        double ang = (double)s * inv;
        double sn, cs;
        sincos(ang, &sn, &cs);
        ct[s * 32 + i] = (float)cs;
        st[s * 32 + i] = (float)sn;
        return;
    }
    int idx = bid - 256;
    int l = idx / 3072;
    int r = idx % 3072;
    const float* W;
    int K, N, t;
    size_t doff;
    if (r < 1024) {
        int m = r >> 8; t = r & 255;
        const float* Ws4 = (m == 0) ? Wq : (m == 1) ? Wk : (m == 2) ? Wv : Wo;
        W = Ws4 + (size_t)l * DIM * DIM;
        K = 512; N = 512;
        doff = (size_t)l * WT_LAYER + (size_t)m * 512 * 512;
    } else if (r < 2048) {
        t = r - 1024;
        W = W1 + (size_t)l * DIM * FF;
        K = 512; N = 2048;
        doff = (size_t)l * WT_LAYER + WT_W1;
    } else {
        t = r - 2048;
        W = W2 + (size_t)l * FF * DIM;
        K = 2048; N = 512;
        doff = (size_t)l * WT_LAYER + WT_W2;
    }
    int ntiles = N >> 5;
    int bx = t % ntiles, by = t / ntiles;
    __shared__ float tile[32][33];
    int n0 = bx * 32, k0 = by * 32;
    int tx = threadIdx.x & 31, ty = threadIdx.x >> 5;
#pragma unroll
    for (int i = 0; i < 32; i += 8)
        tile[ty + i][tx] = W[(size_t)(k0 + ty + i) * N + n0 + tx];
    __syncthreads();
#pragma unroll
    for (int i = 0; i < 32; i += 8) {
        float v = tile[tx][ty + i];
        __nv_bfloat16 h = __float2bfloat16(v);
        __nv_bfloat16 lo = __float2bfloat16(v - __bfloat162float(h));
        size_t o = doff + (size_t)(n0 + ty + i) * K + k0 + tx;
        Th[o] = h; Tl[o] = lo;
    }
}

// ---------------- rmsnorm + bf16 hi/lo split: one WARP per row (no bars) ----------------
__global__ void rmsnorm_split_kernel(const float* __restrict__ x, const float* __restrict__ w,
                                     __nv_bfloat16* __restrict__ hi, __nv_bfloat16* __restrict__ lo) {
    int row = blockIdx.x * 8 + (threadIdx.x >> 5);
    int lane = threadIdx.x & 31;
    const float* xr = x + (size_t)row * DIM;
    float4 v[4];
    float s = 0.f;
#pragma unroll
    for (int k = 0; k < 4; k++) {
        v[k] = *(const float4*)(xr + lane * 4 + k * 128);
        s += v[k].x * v[k].x + v[k].y * v[k].y + v[k].z * v[k].z + v[k].w * v[k].w;
    }
#pragma unroll
    for (int o = 16; o; o >>= 1) s += __shfl_xor_sync(0xffffffffu, s, o);
    float inv = rsqrtf(s * (1.0f / (float)DIM) + 1e-6f);
#pragma unroll
    for (int k = 0; k < 4; k++) {
        float4 wv = *(const float4*)(w + lane * 4 + k * 128);
        float y0 = v[k].x * inv * wv.x;
        float y1 = v[k].y * inv * wv.y;
        float y2 = v[k].z * inv * wv.z;
        float y3 = v[k].w * inv * wv.w;
        uint32_t h01 = pack_bf16x2(y0, y1);
        uint32_t h23 = pack_bf16x2(y2, y3);
        __nv_bfloat162 hA = *(__nv_bfloat162*)&h01;
        __nv_bfloat162 hB = *(__nv_bfloat162*)&h23;
        uint32_t l01 = pack_bf16x2(y0 - __bfloat162float(hA.x), y1 - __bfloat162float(hA.y));
        uint32_t l23 = pack_bf16x2(y2 - __bfloat162float(hB.x), y3 - __bfloat162float(hB.y));
        size_t o = (size_t)row * DIM + lane * 4 + k * 128;
        uint2 hv = {h01, h23}, lv = {l01, l23};
        *(uint2*)(hi + o) = hv;
        *(uint2*)(lo + o) = lv;
    }
}

// ---------------- HMMA flash attention (exact R14-benched version) ----------------
#define AT_STR 72
#define FA_BUF (64*AT_STR)          // elements per operand buffer (4608)
#define FA_STAGE (4*FA_BUF)         // 18432 elements per stage
#define FA_QH_OFF (2*FA_STAGE)      // Q-hi element offset (36864)
#define FA_QBUF (128*AT_STR)        // 9216 elements per Q buffer
#define FA_SMEM ((2*FA_STAGE + 2*FA_QBUF) * 2)   // 110592 bytes

__global__ __launch_bounds__(256, 2)
void fa_kernel(const __nv_bfloat16* __restrict__ Qh, const __nv_bfloat16* __restrict__ Ql,
               const __nv_bfloat16* __restrict__ Kh, const __nv_bfloat16* __restrict__ Kl,
               const __nv_bfloat16* __restrict__ Vh, const __nv_bfloat16* __restrict__ Vl,
               __nv_bfloat16* __restrict__ Ohi, __nv_bfloat16* __restrict__ Olo) {
    extern __shared__ __nv_bfloat16 smb[];
    const uint32_t sbF = smem_u32(smb);

    const int bh = blockIdx.x;
    const int qt = (int)gridDim.y - 1 - (int)blockIdx.y;   // longest first
    const int tid = threadIdx.x, w = tid >> 5, lane = tid & 31;
    const int g = lane >> 2, tg = lane & 3;

    // ldmatrix per-lane offsets
    const uint32_t kboff = (((lane & 7) * AT_STR) + ((lane >> 3) << 3)) * 2;      // B operand
    const uint32_t qfoff = (uint32_t)(FA_QH_OFF + (w * 16 + (lane & 15)) * AT_STR
                                      + ((lane >> 4) << 3)) * 2;                  // A operand (Q)

    // ---- stage Q (128 rows hi + lo) into the dedicated Q region ----
    {
        const __nv_bfloat16* qbh = Qh + ((size_t)bh * SEQ + qt * 128) * DHD;
        const __nv_bfloat16* qbl = Ql + ((size_t)bh * SEQ + qt * 128) * DHD;
        for (int idx = tid; idx < 1024; idx += 256) {
            int r = idx >> 3, c = (idx & 7) << 3;
            *(uint4*)&smb[FA_QH_OFF + r * AT_STR + c]           = *(const uint4*)(qbh + r * DHD + c);
            *(uint4*)&smb[FA_QH_OFF + FA_QBUF + r * AT_STR + c] = *(const uint4*)(qbl + r * DHD + c);
        }
    }

    float accO[8][4] = {};
    float m0 = -1e30f, m1 = -1e30f, l0 = 0.f, l1 = 0.f;
    const int grow0 = qt * 128 + w * 16 + g;
    const int grow1 = grow0 + 8;

    const __nv_bfloat16* kbh = Kh + (size_t)bh * SEQ * DHD;
    const __nv_bfloat16* kbl = Kl + (size_t)bh * SEQ * DHD;
    const __nv_bfloat16* vbh = Vh + (size_t)bh * DHD * SEQ;
    const __nv_bfloat16* vbl = Vl + (size_t)bh * DHD * SEQ;

    const int ntiles = 2 * qt + 2;

    // prologue: stage tile 0 into stage 0
    {
        uint32_t stb = sbF;
        for (int i = 0; i < 2; i++) {
            int idx = tid + i * 256;
            int r = idx >> 3, c = (idx & 7) << 3;
            uint32_t so = stb + (r * AT_STR + c) * 2;
            cp_async16(so,                 kbh + (size_t)r * DHD + c);
            cp_async16(so + FA_BUF * 2,    kbl + (size_t)r * DHD + c);
            cp_async16(so + 2 * FA_BUF * 2, vbh + (size_t)r * SEQ + c);
            cp_async16(so + 3 * FA_BUF * 2, vbl + (size_t)r * SEQ + c);
        }
        CP_COMMIT();
    }

    for (int kt = 0; kt < ntiles; kt++) {
        const int cur = kt & 1;
        if (kt + 1 < ntiles) {
            uint32_t stb = sbF + (cur ^ 1) * FA_STAGE * 2;
            for (int i = 0; i < 2; i++) {
                int idx = tid + i * 256;
                int r = idx >> 3, c = (idx & 7) << 3;
                uint32_t so = stb + (r * AT_STR + c) * 2;
                cp_async16(so,                 kbh + (size_t)((kt + 1) * 64 + r) * DHD + c);
                cp_async16(so + FA_BUF * 2,    kbl + (size_t)((kt + 1) * 64 + r) * DHD + c);
                cp_async16(so + 2 * FA_BUF * 2, vbh + (size_t)r * SEQ + (kt + 1) * 64 + c);
                cp_async16(so + 3 * FA_BUF * 2, vbl + (size_t)r * SEQ + (kt + 1) * 64 + c);
            }
            CP_COMMIT();
            CP_WAIT1();
        } else {
            CP_WAIT0();
        }
        __syncthreads();   // also makes Q staging visible on first iteration

        const uint32_t sKhB = sbF + cur * FA_STAGE * 2;
        const uint32_t sKlB = sKhB + FA_BUF * 2;
        const uint32_t sVhB = sKhB + 2 * FA_BUF * 2;
        const uint32_t sVlB = sKhB + 3 * FA_BUF * 2;

        // S = Q @ K^T  (Q frags reloaded from smem; p-outer keeps only 16 Q regs live)
        float sc[8][4] = {};
#pragma unroll
        for (int p = 0; p < 2; p++) {
            uint32_t qh0[4], qh1[4], ql0[4], ql1[4];
            ldsm_x4(qh0, sbF + qfoff + p * 64);
            ldsm_x4(qh1, sbF + qfoff + p * 64 + 32);
            ldsm_x4(ql0, sbF + qfoff + FA_QBUF * 2 + p * 64);
            ldsm_x4(ql1, sbF + qfoff + FA_QBUF * 2 + p * 64 + 32);
#pragma unroll
            for (int nt = 0; nt < 8; nt++) {
                uint32_t rowb = (uint32_t)(nt * 8 * AT_STR * 2) + kboff;
                uint32_t bkh[4], bkl[4];
                ldsm_x4(bkh, sKhB + rowb + p * 64);
                ldsm_x4(bkl, sKlB + rowb + p * 64);
                mma16816(sc[nt], qh0, bkh);
                mma16816(sc[nt], qh0, bkl);
                mma16816(sc[nt], ql0, bkh);
                mma16816(sc[nt], qh1, bkh + 2);
                mma16816(sc[nt], qh1, bkl + 2);
                mma16816(sc[nt], ql1, bkh + 2);
            }
        }

        // causal mask on the last two tiles
        if (kt >= 2 * qt) {
#pragma unroll
            for (int nt = 0; nt < 8; nt++) {
                int keyg = kt * 64 + nt * 8 + tg * 2;
                if (keyg     > grow0) sc[nt][0] = -1e30f;
                if (keyg + 1 > grow0) sc[nt][1] = -1e30f;
                if (keyg     > grow1) sc[nt][2] = -1e30f;
                if (keyg + 1 > grow1) sc[nt][3] = -1e30f;
            }
        }

        // online softmax
        float mt0 = -1e30f, mt1 = -1e30f;
#pragma unroll
        for (int nt = 0; nt < 8; nt++) {
            mt0 = fmaxf(mt0, fmaxf(sc[nt][0], sc[nt][1]));
            mt1 = fmaxf(mt1, fmaxf(sc[nt][2], sc[nt][3]));
        }
        mt0 = fmaxf(mt0, __shfl_xor_sync(0xffffffffu, mt0, 1));
        mt0 = fmaxf(mt0, __shfl_xor_sync(0xffffffffu, mt0, 2));
        mt1 = fmaxf(mt1, __shfl_xor_sync(0xffffffffu, mt1, 1));
        mt1 = fmaxf(mt1, __shfl_xor_sync(0xffffffffu, mt1, 2));
        float mn0 = fmaxf(m0, mt0), mn1 = fmaxf(m1, mt1);
        float f0 = __expf(m0 - mn0), f1 = __expf(m1 - mn1);
        float s0 = 0.f, s1 = 0.f;
#pragma unroll
        for (int nt = 0; nt < 8; nt++) {
            float p0 = __expf(sc[nt][0] - mn0);
            float p1 = __expf(sc[nt][1] - mn0);
            float p2 = __expf(sc[nt][2] - mn1);
            float p3 = __expf(sc[nt][3] - mn1);
            sc[nt][0] = p0; sc[nt][1] = p1; sc[nt][2] = p2; sc[nt][3] = p3;
            s0 += p0 + p1; s1 += p2 + p3;
        }
        s0 += __shfl_xor_sync(0xffffffffu, s0, 1);
        s0 += __shfl_xor_sync(0xffffffffu, s0, 2);
        s1 += __shfl_xor_sync(0xffffffffu, s1, 1);
        s1 += __shfl_xor_sync(0xffffffffu, s1, 2);
        l0 = l0 * f0 + s0;
        l1 = l1 * f1 + s1;
        m0 = mn0; m1 = mn1;
#pragma unroll
        for (int dt = 0; dt < 8; dt++) {
            accO[dt][0] *= f0; accO[dt][1] *= f0;
            accO[dt][2] *= f1; accO[dt][3] *= f1;
        }

        // O += P @ V (P re-split hi/lo in registers; ldsm_x4 covers two k16 frags)
#pragma unroll
        for (int jp = 0; jp < 2; jp++) {
            uint32_t aPh[2][4], aPl[2][4];
#pragma unroll
            for (int jj = 0; jj < 2; jj++) {
                int j = jp * 2 + jj;
                float x00 = sc[2*j][0],   x01 = sc[2*j][1],   x02 = sc[2*j][2],   x03 = sc[2*j][3];
                float x10 = sc[2*j+1][0], x11 = sc[2*j+1][1], x12 = sc[2*j+1][2], x13 = sc[2*j+1][3];
                aPh[jj][0] = pack_bf16x2(x00, x01);
                aPh[jj][1] = pack_bf16x2(x02, x03);
                aPh[jj][2] = pack_bf16x2(x10, x11);
                aPh[jj][3] = pack_bf16x2(x12, x13);
                __nv_bfloat162* t;
                t = (__nv_bfloat162*)&aPh[jj][0];
                aPl[jj][0] = pack_bf16x2(x00 - __bfloat162float(t->x), x01 - __bfloat162float(t->y));
                t = (__nv_bfloat162*)&aPh[jj][1];
                aPl[jj][1] = pack_bf16x2(x02 - __bfloat162float(t->x), x03 - __bfloat162float(t->y));
                t = (__nv_bfloat162*)&aPh[jj][2];
                aPl[jj][2] = pack_bf16x2(x10 - __bfloat162float(t->x), x11 - __bfloat162float(t->y));
                t = (__nv_bfloat162*)&aPh[jj][3];
                aPl[jj][3] = pack_bf16x2(x12 - __bfloat162float(t->x), x13 - __bfloat162float(t->y));
            }
#pragma unroll
            for (int dt = 0; dt < 8; dt++) {
                uint32_t rb = (uint32_t)(dt * 8 * AT_STR * 2) + kboff + jp * 64;
                uint32_t bvh[4], bvl[4];
                ldsm_x4(bvh, sVhB + rb);
                ldsm_x4(bvl, sVlB + rb);
                mma16816(accO[dt], aPh[0], bvh);
                mma16816(accO[dt], aPh[0], bvl);
                mma16816(accO[dt], aPl[0], bvh);
                mma16816(accO[dt], aPh[1], bvh + 2);
                mma16816(accO[dt], aPh[1], bvl + 2);
                mma16816(accO[dt], aPl[1], bvh + 2);
            }
        }
        __syncthreads();
    }

    // epilogue -> (B,S,D) bf16 hi/lo
    float il0 = 1.0f / l0, il1 = 1.0f / l1;
    int b = bh >> 3, h = bh & 7;
    size_t row0 = (size_t)b * SEQ + qt * 128 + w * 16 + g;
    size_t row1 = row0 + 8;
#pragma unroll
    for (int dt = 0; dt < 8; dt++) {
        int col = h * DHD + dt * 8 + tg * 2;
        float o0 = accO[dt][0] * il0, o1 = accO[dt][1] * il0;
        float o2 = accO[dt][2] * il1, o3 = accO[dt][3] * il1;
        __nv_bfloat16 h0 = __float2bfloat16(o0), h1 = __float2bfloat16(o1);
        __nv_bfloat16 h2 = __float2bfloat16(o2), h3 = __float2bfloat16(o3);
        *(__nv_bfloat162*)(Ohi + row0 * DIM + col) = {h0, h1};
        *(__nv_bfloat162*)(Ohi + row1 * DIM + col) = {h2, h3};
        *(__nv_bfloat162*)(Olo + row0 * DIM + col) =
            {__float2bfloat16(o0 - __bfloat162float(h0)), __float2bfloat16(o1 - __bfloat162float(h1))};
        *(__nv_bfloat162*)(Olo + row1 * DIM + col) =
            {__float2bfloat16(o2 - __bfloat162float(h2)), __float2bfloat16(o3 - __bfloat162float(h3))};
    }
}

// ---------------- head: logits -> sigmoid probs ----------------
__global__ void head_kernel(const float* __restrict__ X, const float* __restrict__ hw,
                            const float* __restrict__ hb, float* __restrict__ probs) {
    int row = blockIdx.x * 8 + (threadIdx.x >> 5);
    int lane = threadIdx.x & 31;
    const float* xr = X + (size_t)row * DIM;
    float s = 0.f;
    for (int i = lane; i < DIM; i += 32) s = fmaf(xr[i], hw[i], s);
#pragma unroll
    for (int o = 16; o; o >>= 1) s += __shfl_xor_sync(0xffffffffu, s, o);
    if (lane == 0) {
        float logit = s + hb[0];
        probs[row] = 1.0f / (1.0f + expf(-logit));
    }
}

// ---------------- chunking (serial boundaries in smem, parallel id fill) ----------------
__global__ void chunk_kernel(const float* __restrict__ probs, int* __restrict__ ids,
                             int* __restrict__ nch, float* __restrict__ psum) {
    int b = blockIdx.x, t = threadIdx.x;
    __shared__ int flags[SEQ];
    __shared__ int ids_s[SEQ];
    __shared__ float red[256];
    const float* pr = probs + (size_t)b * SEQ;
    float s = 0.f; int any = 0;
    for (int i = t; i < SEQ; i += 256) {
        float p = pr[i];
        int f = (p > 0.5f) ? 1 : 0;
        flags[i] = f; s += p; any |= f;
    }
    red[t] = s;
    __syncthreads();
#pragma unroll
    for (int o = 128; o > 0; o >>= 1) {
        if (t < o) red[t] += red[t + o];
        __syncthreads();
    }
    int anyflag = __syncthreads_or(any);
    if (t == 0) {
        psum[b] = red[0];
        int cur_end = 0, cid = -1;
        for (int tt = 0; tt < SEQ; tt++) {
            if (tt == cur_end) {
                int cap = tt + 16; if (cap > SEQ) cap = SEQ;
                int e = cap;
                for (int ss = tt + 1; ss <= cap; ss++) {
                    int he = anyflag ? flags[ss - 1] : (ss == SEQ - 1);
                    if (he) { e = ss; break; }
                }
                if (e - tt < 3) { e = tt + 3; if (e > SEQ) e = SEQ; }
                cur_end = e; cid++;
            }
            ids_s[tt] = cid;
        }
        nch[b] = cid + 1;
    }
    __syncthreads();
    for (int i = t; i < SEQ; i += 256) ids[b * SEQ + i] = ids_s[i];
}

// ---------------- mask ----------------
__global__ void mask_kernel(const int* __restrict__ ids, float* __restrict__ out) {
    int i4 = blockIdx.x * 256 + threadIdx.x;
    int j = (i4 & 511) << 2;
    int rowIdx = i4 >> 9;
    int b = rowIdx >> 11;
    int idi = ids[rowIdx];
    const int* idr = ids + b * SEQ;
    size_t base = ((size_t)rowIdx << 11) + j;
    out[base + 0] = (idi == idr[j + 0]) ? 1.f : 0.f;
    out[base + 1] = (idi == idr[j + 1]) ? 1.f : 0.f;
    out[base + 2] = (idi == idr[j + 2]) ? 1.f : 0.f;
    out[base + 3] = (idi == idr[j + 3]) ? 1.f : 0.f;
}

__global__ void scalars_kernel(const int* __restrict__ nch, const float* __restrict__ psum,
                               float* __restrict__ out_acl, float* __restrict__ out_cll) {
    float a = 0.f, c = 0.f;
    for (int b = 0; b < NUM_B; b++) {
        a += (float)SEQ / (float)nch[b];
        c += psum[b];
    }
    *out_acl = a * 0.25f;
    *out_cll = c * 0.25f;
}

__global__ void xids_kernel(const int* __restrict__ xids, float* __restrict__ out) {
    int i = blockIdx.x * 256 + threadIdx.x;
    out[i] = (float)xids[i];
}

// ---------------- launch ----------------
extern "C" void kernel_launch(void* const* d_in, const int* in_sizes, int n_in,
                              void* d_out, int out_size) {
    const float* x    = (const float*)d_in[0];
    const int*   xids = (const int*)  d_in[1];
    const float* ln1  = (const float*)d_in[2];
    const float* Wq   = (const float*)d_in[3];
    const float* Wk   = (const float*)d_in[4];
    const float* Wv   = (const float*)d_in[5];
    const float* Wo   = (const float*)d_in[6];
    const float* ln2  = (const float*)d_in[7];
    const float* W1   = (const float*)d_in[8];
    const float* W2   = (const float*)d_in[9];
    const float* hw   = (const float*)d_in[10];
    const float* hb   = (const float*)d_in[11];
    float* out = (float*)d_out;

    float *X, *probs, *psum, *rc, *rs;
    __nv_bfloat16 *Ahi, *Alo, *Ghi, *Glo, *WThi, *WTlo;
    __nv_bfloat16 *Qbh, *Qbl, *Kbh, *Kbl, *Vbh, *Vbl;
    int *ids, *nch;
    cudaGetSymbolAddress((void**)&X,  g_X);
    cudaGetSymbolAddress((void**)&Qbh, g_Qbh);
    cudaGetSymbolAddress((void**)&Qbl, g_Qbl);
    cudaGetSymbolAddress((void**)&Kbh, g_Kbh);
    cudaGetSymbolAddress((void**)&Kbl, g_Kbl);
    cudaGetSymbolAddress((void**)&Vbh, g_Vbh);
    cudaGetSymbolAddress((void**)&Vbl, g_Vbl);
    cudaGetSymbolAddress((void**)&Ahi, g_Ahi);
    cudaGetSymbolAddress((void**)&Alo, g_Alo);
    cudaGetSymbolAddress((void**)&Ghi, g_Ghi);
    cudaGetSymbolAddress((void**)&Glo, g_Glo);
    cudaGetSymbolAddress((void**)&WThi, g_WThi);
    cudaGetSymbolAddress((void**)&WTlo, g_WTlo);
    cudaGetSymbolAddress((void**)&probs, g_probs);
    cudaGetSymbolAddress((void**)&psum,  g_psum);
    cudaGetSymbolAddress((void**)&ids, g_ids);
    cudaGetSymbolAddress((void**)&nch, g_nch);
    cudaGetSymbolAddress((void**)&rc, g_rc);
    cudaGetSymbolAddress((void**)&rs, g_rs);

    cudaFuncSetAttribute(hmma_gemm_kernel<1>, cudaFuncAttributeMaxDynamicSharedMemorySize, GM_SMEM2);
    cudaFuncSetAttribute(hmma_gemm_kernel<3>, cudaFuncAttributeMaxDynamicSharedMemorySize, GM_SMEM2);
    cudaFuncSetAttribute(hmma_gemm_qkv, cudaFuncAttributeMaxDynamicSharedMemorySize, GM_SMEM2);
    cudaFuncSetAttribute(fa_kernel, cudaFuncAttributeMaxDynamicSharedMemorySize, FA_SMEM);

    // fused prep: rope table + all weight transposes/splits in one launch
    prep_kernel<<<256 + NLAYER * 3072, 256>>>(Wq, Wk, Wv, Wo, W1, W2, WThi, WTlo, rc, rs);
    cudaMemcpyAsync(X, x, sizeof(float) * (size_t)ROWS * DIM, cudaMemcpyDeviceToDevice, 0);

    dim3 g512(DIM / 128, ROWS / 128);   // (4, 64)
    dim3 gqkv(12, ROWS / 128);          // fused QKV: 3 x 4 n-blocks
    dim3 gff (FF  / 128, ROWS / 128);   // (16, 64)
    dim3 gfa (NUM_B * NH, SEQ / 128);   // bh fastest, qt reversed inside

    for (int l = 0; l < NLAYER; l++) {
        const __nv_bfloat16* th = WThi + (size_t)l * WT_LAYER;
        const __nv_bfloat16* tl = WTlo + (size_t)l * WT_LAYER;

        rmsnorm_split_kernel<<<ROWS / 8, 256>>>(X, ln1 + l * DIM, Ahi, Alo);
        hmma_gemm_qkv<<<gqkv, 256, GM_SMEM2>>>(Ahi, Alo, th, tl,
                                               Qbh, Qbl, Kbh, Kbl, Vbh, Vbl, rc, rs);
        fa_kernel<<<gfa, 256, FA_SMEM>>>(Qbh, Qbl, Kbh, Kbl, Vbh, Vbl, Ahi, Alo);
        hmma_gemm_kernel<1><<<g512, 256, GM_SMEM2>>>(Ahi, Alo, th + WT_O, tl + WT_O,
                                                     X, X, nullptr, nullptr, ROWS, DIM, DIM);
        rmsnorm_split_kernel<<<ROWS / 8, 256>>>(X, ln2 + l * DIM, Ahi, Alo);
        hmma_gemm_kernel<3><<<gff, 256, GM_SMEM2>>>(Ahi, Alo, th + WT_W1, tl + WT_W1,
                                                    nullptr, nullptr, Ghi, Glo, ROWS, FF, DIM);
        hmma_gemm_kernel<1><<<g512, 256, GM_SMEM2>>>(Ghi, Glo, th + WT_W2, tl + WT_W2,
                                                     X, X, nullptr, nullptr, ROWS, DIM, FF);
    }

    head_kernel <<<ROWS / 8, 256>>>(X, hw, hb, probs);
    chunk_kernel<<<NUM_B, 256>>>(probs, ids, nch, psum);
    mask_kernel <<<(N_MASK / 4) / 256, 256>>>(ids, out + OFF_MASK);
    scalars_kernel<<<1, 1>>>(nch, psum, out + OFF_ACL, out + OFF_CLL);
    xids_kernel <<<ROWS / 256, 256>>>(xids, out + OFF_IDS);
    cudaMemcpyAsync(out + OFF_XT, X, sizeof(float) * (size_t)ROWS * DIM, cudaMemcpyDeviceToDevice, 0);
}

// round 17
// speedup vs baseline: 1.0779x; 1.0010x over previous
#include <cuda_runtime.h>
#include <cuda_bf16.h>
#include <math.h>
#include <stdint.h>
#include <stddef.h>

// ---------------- problem constants ----------------
#define NUM_B 4
#define SEQ   2048
#define DIM   512
#define NH    8
#define DHD   64
#define FF    2048
#define ROWS  (NUM_B*SEQ)          // 8192
#define NLAYER 2

// output layout (float32, concatenated in reference return order)
#define OFF_XT   0
#define N_XT     (ROWS*DIM)                 // 4194304
#define OFF_IDS  (OFF_XT + N_XT)            // 4194304
#define N_IDS    (ROWS)                     // 8192
#define OFF_ACL  (OFF_IDS + N_IDS)          // 4202496
#define OFF_MASK (OFF_ACL + 1)              // 4202497 (odd -> scalar stores only)
#define N_MASK   (NUM_B*SEQ*SEQ)            // 16777216
#define OFF_CLL  (OFF_MASK + N_MASK)        // 20979713

// per-layer transposed-weight bf16 buffer layout (elements)
#define WT_Q   0
#define WT_K   (512*512)
#define WT_V   (2*512*512)
#define WT_O   (3*512*512)
#define WT_W1  (4*512*512)                  // [2048][512]
#define WT_W2  (4*512*512 + 2048*512)       // [512][2048]
#define WT_LAYER (4*512*512 + 2*2048*512)   // 3145728

// ---------------- scratch (device globals; no allocation allowed) ----------------
__device__ float g_X [ROWS*DIM];
__device__ __nv_bfloat16 g_Qbh[ROWS*DIM];   // (B,H,S,Dh) hi, pre-scaled 1/8
__device__ __nv_bfloat16 g_Qbl[ROWS*DIM];
__device__ __nv_bfloat16 g_Kbh[ROWS*DIM];   // (B,H,S,Dh)
__device__ __nv_bfloat16 g_Kbl[ROWS*DIM];
__device__ __nv_bfloat16 g_Vbh[ROWS*DIM];   // (B,H,Dh,S)
__device__ __nv_bfloat16 g_Vbl[ROWS*DIM];
__device__ __nv_bfloat16 g_Ahi[ROWS*DIM];
__device__ __nv_bfloat16 g_Alo[ROWS*DIM];
__device__ __nv_bfloat16 g_Ghi[ROWS*FF];
__device__ __nv_bfloat16 g_Glo[ROWS*FF];
__device__ __nv_bfloat16 g_WThi[NLAYER*WT_LAYER];
__device__ __nv_bfloat16 g_WTlo[NLAYER*WT_LAYER];
__device__ float g_probs[ROWS];
__device__ int   g_ids[ROWS];
__device__ int   g_nch[NUM_B];
__device__ float g_psum[NUM_B];
__device__ float g_rc[SEQ*32];
__device__ float g_rs[SEQ*32];

// ---------------- low-level helpers ----------------
__device__ __forceinline__ void mma16816(float* c, const uint32_t* a, const uint32_t* b) {
    asm volatile(
        "mma.sync.aligned.m16n8k16.row.col.f32.bf16.bf16.f32 "
        "{%0,%1,%2,%3}, {%4,%5,%6,%7}, {%8,%9}, {%0,%1,%2,%3};"
        : "+f"(c[0]), "+f"(c[1]), "+f"(c[2]), "+f"(c[3])
        : "r"(a[0]), "r"(a[1]), "r"(a[2]), "r"(a[3]), "r"(b[0]), "r"(b[1]));
}

__device__ __forceinline__ uint32_t pack_bf16x2(float x, float y) {
    __nv_bfloat162 t;
    t.x = __float2bfloat16(x);
    t.y = __float2bfloat16(y);
    return *(uint32_t*)&t;
}

__device__ __forceinline__ uint32_t smem_u32(const void* p) {
    uint32_t a;
    asm("{ .reg .u64 t; cvta.to.shared.u64 t, %1; cvt.u32.u64 %0, t; }" : "=r"(a) : "l"(p));
    return a;
}

__device__ __forceinline__ void cp_async16(uint32_t saddr, const void* gaddr) {
    asm volatile("cp.async.ca.shared.global [%0], [%1], 16;" :: "r"(saddr), "l"(gaddr));
}
#define CP_COMMIT() asm volatile("cp.async.commit_group;" ::: "memory")
#define CP_WAIT1()  asm volatile("cp.async.wait_group 1;" ::: "memory")
#define CP_WAIT0()  asm volatile("cp.async.wait_group 0;" ::: "memory")

__device__ __forceinline__ void ldsm_x4(uint32_t* r, uint32_t saddr) {
    asm volatile("ldmatrix.sync.aligned.m8n8.x4.shared.b16 {%0,%1,%2,%3}, [%4];"
        : "=r"(r[0]), "=r"(r[1]), "=r"(r[2]), "=r"(r[3]) : "r"(saddr));
}
__device__ __forceinline__ void ldsm_x2(uint32_t* r, uint32_t saddr) {
    asm volatile("ldmatrix.sync.aligned.m8n8.x2.shared.b16 {%0,%1}, [%2];"
        : "=r"(r[0]), "=r"(r[1]) : "r"(saddr));
}

// ---------------- GEMM mainloop (R14 staging; MMA stream reordered term-major) -------
#define SKP 40                       // padded smem row stride (elements); 80B
#define GBUF (128*SKP)               // elements per operand buffer
#define GSTAGE (4*GBUF)              // elements per stage (Ah,Al,Bh,Bl)
#define GM_SMEM2 (2*GSTAGE*2)        // 81920 bytes (also >= 128*129*4 epilogue tile)

__device__ __forceinline__ void gemm_mainloop(
        __nv_bfloat16* smg,
        const __nv_bfloat16* __restrict__ Ahi, const __nv_bfloat16* __restrict__ Alo,
        const __nv_bfloat16* __restrict__ Bhi, const __nv_bfloat16* __restrict__ Blo,
        int bm, int bn, int K, float acc[4][4][4],
        int tid, int wm, int wn, int lane) {
    const uint32_t sb = smem_u32(smg);
    const int cr0 = tid >> 2, cko0 = (tid & 3) << 3;
    const int cr1 = (tid + 256) >> 2, cko1 = ((tid + 256) & 3) << 3;

    uint32_t aoff[2], boff[2];
    {
        int arow = (lane & 15), acol8 = (lane >> 4) << 3;
        int lb = lane & 15;
        int brow = (lb & 7), bcol8 = (lb >> 3) << 3;
#pragma unroll
        for (int ks = 0; ks < 2; ks++) {
            aoff[ks] = ((wm + arow) * SKP + ks * 16 + acol8) * 2;
            boff[ks] = ((wn + brow) * SKP + ks * 16 + bcol8) * 2 + 2 * GBUF * 2;
        }
    }

    const int nchunk = K >> 5;
    // prologue: stage chunk 0 into stage 0
    {
        const __nv_bfloat16* pAh = Ahi + (size_t)bm * K;
        const __nv_bfloat16* pAl = Alo + (size_t)bm * K;
        const __nv_bfloat16* pBh = Bhi + (size_t)bn * K;
        const __nv_bfloat16* pBl = Blo + (size_t)bn * K;
        uint32_t s0 = sb + (cr0 * SKP + cko0) * 2;
        uint32_t s1 = sb + (cr1 * SKP + cko1) * 2;
        size_t g0 = (size_t)cr0 * K + cko0;
        size_t g1 = (size_t)cr1 * K + cko1;
        cp_async16(s0,                pAh + g0);
        cp_async16(s0 + GBUF * 2,     pAl + g0);
        cp_async16(s0 + 2 * GBUF * 2, pBh + g0);
        cp_async16(s0 + 3 * GBUF * 2, pBl + g0);
        cp_async16(s1,                pAh + g1);
        cp_async16(s1 + GBUF * 2,     pAl + g1);
        cp_async16(s1 + 2 * GBUF * 2, pBh + g1);
        cp_async16(s1 + 3 * GBUF * 2, pBl + g1);
        CP_COMMIT();
    }

    for (int kc = 0; kc < nchunk; kc++) {
        const int cur = kc & 1;
        if (kc + 1 < nchunk) {
            const int nxt = cur ^ 1;
            const __nv_bfloat16* pAh = Ahi + (size_t)bm * K + (size_t)(kc + 1) * 32;
            const __nv_bfloat16* pAl = Alo + (size_t)bm * K + (size_t)(kc + 1) * 32;
            const __nv_bfloat16* pBh = Bhi + (size_t)bn * K + (size_t)(kc + 1) * 32;
            const __nv_bfloat16* pBl = Blo + (size_t)bn * K + (size_t)(kc + 1) * 32;
            uint32_t stb = sb + nxt * GSTAGE * 2;
            uint32_t s0 = stb + (cr0 * SKP + cko0) * 2;
            uint32_t s1 = stb + (cr1 * SKP + cko1) * 2;
            size_t g0 = (size_t)cr0 * K + cko0;
            size_t g1 = (size_t)cr1 * K + cko1;
            cp_async16(s0,                pAh + g0);
            cp_async16(s0 + GBUF * 2,     pAl + g0);
            cp_async16(s0 + 2 * GBUF * 2, pBh + g0);
            cp_async16(s0 + 3 * GBUF * 2, pBl + g0);
            cp_async16(s1,                pAh + g1);
            cp_async16(s1 + GBUF * 2,     pAl + g1);
            cp_async16(s1 + 2 * GBUF * 2, pBh + g1);
            cp_async16(s1 + 3 * GBUF * 2, pBl + g1);
            CP_COMMIT();
            CP_WAIT1();
        } else {
            CP_WAIT0();
        }
        __syncthreads();

        const uint32_t stg = sb + cur * GSTAGE * 2;
#pragma unroll
        for (int ks = 0; ks < 2; ks++) {
            uint32_t bh[4][2], bl[4][2];
#pragma unroll
            for (int nt = 0; nt < 4; nt++) {
                ldsm_x2(bh[nt], stg + boff[ks] + nt * 8 * SKP * 2);
                ldsm_x2(bl[nt], stg + boff[ks] + nt * 8 * SKP * 2 + GBUF * 2);
            }
#pragma unroll
            for (int mt = 0; mt < 4; mt++) {
                uint32_t ah[4], al[4];
                ldsm_x4(ah, stg + aoff[ks] + mt * 16 * SKP * 2);
                ldsm_x4(al, stg + aoff[ks] + mt * 16 * SKP * 2 + GBUF * 2);
                // term-major order: same-accumulator distance 4 (was 1);
                // per-accumulator term order unchanged (hh, hl, lh) -> bitwise identical
#pragma unroll
                for (int nt = 0; nt < 4; nt++)
                    mma16816(acc[mt][nt], ah, bh[nt]);
#pragma unroll
                for (int nt = 0; nt < 4; nt++)
                    mma16816(acc[mt][nt], ah, bl[nt]);
#pragma unroll
                for (int nt = 0; nt < 4; nt++)
                    mma16816(acc[mt][nt], al, bh[nt]);
            }
        }
        __syncthreads();
    }
}

// generic GEMM. EPI: 0 store fp32, 1 residual add, 3 gelu -> bf16 hi/lo split
template<int EPI>
__global__ __launch_bounds__(256, 2)
void hmma_gemm_kernel(const __nv_bfloat16* __restrict__ Ahi, const __nv_bfloat16* __restrict__ Alo,
                      const __nv_bfloat16* __restrict__ Bhi, const __nv_bfloat16* __restrict__ Blo,
                      const float* __restrict__ Cin, float* __restrict__ C,
                      __nv_bfloat16* __restrict__ Ghi, __nv_bfloat16* __restrict__ Glo,
                      int M, int N, int K) {
    extern __shared__ __nv_bfloat16 smg[];
    const int tid = threadIdx.x;
    const int bm = blockIdx.y * 128, bn = blockIdx.x * 128;
    const int w = tid >> 5, lane = tid & 31;
    const int wm = (w & 1) * 64, wn = (w >> 1) * 32;
    const int g = lane >> 2, tg = lane & 3;

    float acc[4][4][4] = {};
    gemm_mainloop(smg, Ahi, Alo, Bhi, Blo, bm, bn, K, acc, tid, wm, wn, lane);

#pragma unroll
    for (int mt = 0; mt < 4; mt++) {
        int row0 = bm + wm + mt * 16 + g;
        int row1 = row0 + 8;
#pragma unroll
        for (int nt = 0; nt < 4; nt++) {
            int col = bn + wn + nt * 8 + tg * 2;
            float c0 = acc[mt][nt][0], c1 = acc[mt][nt][1];
            float c2 = acc[mt][nt][2], c3 = acc[mt][nt][3];
            if (EPI == 0 || EPI == 1) {
                if (EPI == 1) {
                    float2 r0 = *(const float2*)(Cin + (size_t)row0 * N + col);
                    float2 r1 = *(const float2*)(Cin + (size_t)row1 * N + col);
                    c0 += r0.x; c1 += r0.y; c2 += r1.x; c3 += r1.y;
                }
                float2 v0 = {c0, c1}, v1 = {c2, c3};
                *(float2*)(C + (size_t)row0 * N + col) = v0;
                *(float2*)(C + (size_t)row1 * N + col) = v1;
            } else {
                float vv[4] = {c0, c1, c2, c3};
                __nv_bfloat16 h[4], l[4];
#pragma unroll
                for (int e = 0; e < 4; e++) {
                    float v = vv[e];
                    v = 0.5f * v * (1.0f + erff(v * 0.70710678118654752f));
                    h[e] = __float2bfloat16(v);
                    l[e] = __float2bfloat16(v - __bfloat162float(h[e]));
                }
                *(__nv_bfloat162*)(Ghi + (size_t)row0 * N + col) = {h[0], h[1]};
                *(__nv_bfloat162*)(Ghi + (size_t)row1 * N + col) = {h[2], h[3]};
                *(__nv_bfloat162*)(Glo + (size_t)row0 * N + col) = {l[0], l[1]};
                *(__nv_bfloat162*)(Glo + (size_t)row1 * N + col) = {l[2], l[3]};
            }
        }
    }
}

// fused QKV GEMM + rope/transpose epilogue.
// grid (12, 64); sel = blockIdx.x>>2 picks {Q,K,V}, (x&3) = 128-col n-block.
// Q/K: rope -> bf16 hi/lo in (B,H,S,Dh) (Q pre-scaled 1/8). V: transpose -> (B,H,Dh,S).
__global__ __launch_bounds__(256, 2)
void hmma_gemm_qkv(const __nv_bfloat16* __restrict__ Ahi, const __nv_bfloat16* __restrict__ Alo,
                   const __nv_bfloat16* __restrict__ WTh, const __nv_bfloat16* __restrict__ WTl,
                   __nv_bfloat16* __restrict__ Qoh, __nv_bfloat16* __restrict__ Qol,
                   __nv_bfloat16* __restrict__ Koh, __nv_bfloat16* __restrict__ Kol,
                   __nv_bfloat16* __restrict__ Voh, __nv_bfloat16* __restrict__ Vol,
                   const float* __restrict__ ct, const float* __restrict__ st) {
    extern __shared__ __nv_bfloat16 smg[];
    const int tid = threadIdx.x;
    const int sel = blockIdx.x >> 2;
    const int bm = blockIdx.y * 128, bn = (blockIdx.x & 3) * 128;
    const int w = tid >> 5, lane = tid & 31;
    const int wm = (w & 1) * 64, wn = (w >> 1) * 32;
    const int g = lane >> 2, tg = lane & 3;

    const __nv_bfloat16* Bhi = WTh + (size_t)sel * 512 * 512;
    const __nv_bfloat16* Blo = WTl + (size_t)sel * 512 * 512;

    float acc[4][4][4] = {};
    gemm_mainloop(smg, Ahi, Alo, Bhi, Blo, bm, bn, DIM, acc, tid, wm, wn, lane);

    // stage fp32 tile to smem (stride 129; mainloop ended on a bar, smem free)
    float* ft = (float*)smg;
#pragma unroll
    for (int mt = 0; mt < 4; mt++) {
        int r0 = wm + mt * 16 + g, r1 = r0 + 8;
#pragma unroll
        for (int nt = 0; nt < 4; nt++) {
            int c = wn + nt * 8 + tg * 2;
            ft[r0 * 129 + c]     = acc[mt][nt][0];
            ft[r0 * 129 + c + 1] = acc[mt][nt][1];
            ft[r1 * 129 + c]     = acc[mt][nt][2];
            ft[r1 * 129 + c + 1] = acc[mt][nt][3];
        }
    }
    __syncthreads();

    const int b  = bm >> 11;            // batch (128 | 2048 => tile within one batch)
    const int s0 = bm & (SEQ - 1);
    const int h0 = bn >> 6;             // first head in this 128-col block

    if (sel < 2) {
        const float scale = (sel == 0) ? 0.125f : 1.0f;
        __nv_bfloat16* oh = (sel == 0) ? Qoh : Koh;
        __nv_bfloat16* ol = (sel == 0) ? Qol : Kol;
#pragma unroll
        for (int k = 0; k < 32; k++) {
            int idx = tid + k * 256;            // 8192 pairs
            int i  = idx & 31;
            int lh = (idx >> 5) & 1;
            int r  = idx >> 6;
            int s  = s0 + r;
            float t1 = ft[r * 129 + lh * 64 + i];
            float t2 = ft[r * 129 + lh * 64 + i + 32];
            float c  = ct[s * 32 + i];
            float si = st[s * 32 + i];
            float y0 = (t1 * c - t2 * si) * scale;
            float y1 = (t1 * si + t2 * c) * scale;
            size_t base = (((size_t)(b * NH + h0 + lh)) * SEQ + s) * DHD;
            __nv_bfloat16 hh0 = __float2bfloat16(y0);
            __nv_bfloat16 hh1 = __float2bfloat16(y1);
            oh[base + i]      = hh0;
            ol[base + i]      = __float2bfloat16(y0 - __bfloat162float(hh0));
            oh[base + i + 32] = hh1;
            ol[base + i + 32] = __float2bfloat16(y1 - __bfloat162float(hh1));
        }
    } else {
#pragma unroll
        for (int k = 0; k < 64; k++) {
            int idx = tid + k * 256;            // 16384 elements
            int r = idx & 127;
            int c = idx >> 7;
            float v = ft[r * 129 + c];
            int d = c & 63, lh = c >> 6;
            size_t o = ((size_t)(b * NH + h0 + lh) * DHD + d) * SEQ + s0 + r;
            __nv_bfloat16 hh = __float2bfloat16(v);
            Voh[o] = hh;
            Vol[o] = __float2bfloat16(v - __bfloat162float(hh));
        }
    }
}

// ---------------- fused prep: rope table + all 12 weight transposes/splits ----------------
__global__ void prep_kernel(const float* __restrict__ Wq, const float* __restrict__ Wk,
                            const float* __restrict__ Wv, const float* __restrict__ Wo,
                            const float* __restrict__ W1, const float* __restrict__ W2,
                            __nv_bfloat16* __restrict__ Th, __nv_bfloat16* __restrict__ Tl,
                            float* __restrict__ ct, float* __restrict__ st) {
    int bid = blockIdx.x;
    if (bid < 256) {
        int i = threadIdx.x & 31;
        int s = bid * 8 + (threadIdx.x >> 5);
        double inv = pow(10000.0, -(double)i / 32.0);
        double ang = (double)s * inv;
        double sn, cs;
        sincos(ang, &sn, &cs);
        ct[s * 32 + i] = (float)cs;
        st[s * 32 + i] = (float)sn;
        return;
    }
    int idx = bid - 256;
    int l = idx / 3072;
    int r = idx % 3072;
    const float* W;
    int K, N, t;
    size_t doff;
    if (r < 1024) {
        int m = r >> 8; t = r & 255;
        const float* Ws4 = (m == 0) ? Wq : (m == 1) ? Wk : (m == 2) ? Wv : Wo;
        W = Ws4 + (size_t)l * DIM * DIM;
        K = 512; N = 512;
        doff = (size_t)l * WT_LAYER + (size_t)m * 512 * 512;
    } else if (r < 2048) {
        t = r - 1024;
        W = W1 + (size_t)l * DIM * FF;
        K = 512; N = 2048;
        doff = (size_t)l * WT_LAYER + WT_W1;
    } else {
        t = r - 2048;
        W = W2 + (size_t)l * FF * DIM;
        K = 2048; N = 512;
        doff = (size_t)l * WT_LAYER + WT_W2;
    }
    int ntiles = N >> 5;
    int bx = t % ntiles, by = t / ntiles;
    __shared__ float tile[32][33];
    int n0 = bx * 32, k0 = by * 32;
    int tx = threadIdx.x & 31, ty = threadIdx.x >> 5;
#pragma unroll
    for (int i = 0; i < 32; i += 8)
        tile[ty + i][tx] = W[(size_t)(k0 + ty + i) * N + n0 + tx];
    __syncthreads();
#pragma unroll
    for (int i = 0; i < 32; i += 8) {
        float v = tile[tx][ty + i];
        __nv_bfloat16 h = __float2bfloat16(v);
        __nv_bfloat16 lo = __float2bfloat16(v - __bfloat162float(h));
        size_t o = doff + (size_t)(n0 + ty + i) * K + k0 + tx;
        Th[o] = h; Tl[o] = lo;
    }
}

// ---------------- rmsnorm + bf16 hi/lo split: one WARP per row (no bars) ----------------
__global__ void rmsnorm_split_kernel(const float* __restrict__ x, const float* __restrict__ w,
                                     __nv_bfloat16* __restrict__ hi, __nv_bfloat16* __restrict__ lo) {
    int row = blockIdx.x * 8 + (threadIdx.x >> 5);
    int lane = threadIdx.x & 31;
    const float* xr = x + (size_t)row * DIM;
    float4 v[4];
    float s = 0.f;
#pragma unroll
    for (int k = 0; k < 4; k++) {
        v[k] = *(const float4*)(xr + lane * 4 + k * 128);
        s += v[k].x * v[k].x + v[k].y * v[k].y + v[k].z * v[k].z + v[k].w * v[k].w;
    }
#pragma unroll
    for (int o = 16; o; o >>= 1) s += __shfl_xor_sync(0xffffffffu, s, o);
    float inv = rsqrtf(s * (1.0f / (float)DIM) + 1e-6f);
#pragma unroll
    for (int k = 0; k < 4; k++) {
        float4 wv = *(const float4*)(w + lane * 4 + k * 128);
        float y0 = v[k].x * inv * wv.x;
        float y1 = v[k].y * inv * wv.y;
        float y2 = v[k].z * inv * wv.z;
        float y3 = v[k].w * inv * wv.w;
        uint32_t h01 = pack_bf16x2(y0, y1);
        uint32_t h23 = pack_bf16x2(y2, y3);
        __nv_bfloat162 hA = *(__nv_bfloat162*)&h01;
        __nv_bfloat162 hB = *(__nv_bfloat162*)&h23;
        uint32_t l01 = pack_bf16x2(y0 - __bfloat162float(hA.x), y1 - __bfloat162float(hA.y));
        uint32_t l23 = pack_bf16x2(y2 - __bfloat162float(hB.x), y3 - __bfloat162float(hB.y));
        size_t o = (size_t)row * DIM + lane * 4 + k * 128;
        uint2 hv = {h01, h23}, lv = {l01, l23};
        *(uint2*)(hi + o) = hv;
        *(uint2*)(lo + o) = lv;
    }
}

// ---------------- HMMA flash attention (exact R14/R16-benched version) ----------------
#define AT_STR 72
#define FA_BUF (64*AT_STR)          // elements per operand buffer (4608)
#define FA_STAGE (4*FA_BUF)         // 18432 elements per stage
#define FA_QH_OFF (2*FA_STAGE)      // Q-hi element offset (36864)
#define FA_QBUF (128*AT_STR)        // 9216 elements per Q buffer
#define FA_SMEM ((2*FA_STAGE + 2*FA_QBUF) * 2)   // 110592 bytes

__global__ __launch_bounds__(256, 2)
void fa_kernel(const __nv_bfloat16* __restrict__ Qh, const __nv_bfloat16* __restrict__ Ql,
               const __nv_bfloat16* __restrict__ Kh, const __nv_bfloat16* __restrict__ Kl,
               const __nv_bfloat16* __restrict__ Vh, const __nv_bfloat16* __restrict__ Vl,
               __nv_bfloat16* __restrict__ Ohi, __nv_bfloat16* __restrict__ Olo) {
    extern __shared__ __nv_bfloat16 smb[];
    const uint32_t sbF = smem_u32(smb);

    const int bh = blockIdx.x;
    const int qt = (int)gridDim.y - 1 - (int)blockIdx.y;   // longest first
    const int tid = threadIdx.x, w = tid >> 5, lane = tid & 31;
    const int g = lane >> 2, tg = lane & 3;

    // ldmatrix per-lane offsets
    const uint32_t kboff = (((lane & 7) * AT_STR) + ((lane >> 3) << 3)) * 2;      // B operand
    const uint32_t qfoff = (uint32_t)(FA_QH_OFF + (w * 16 + (lane & 15)) * AT_STR
                                      + ((lane >> 4) << 3)) * 2;                  // A operand (Q)

    // ---- stage Q (128 rows hi + lo) into the dedicated Q region ----
    {
        const __nv_bfloat16* qbh = Qh + ((size_t)bh * SEQ + qt * 128) * DHD;
        const __nv_bfloat16* qbl = Ql + ((size_t)bh * SEQ + qt * 128) * DHD;
        for (int idx = tid; idx < 1024; idx += 256) {
            int r = idx >> 3, c = (idx & 7) << 3;
            *(uint4*)&smb[FA_QH_OFF + r * AT_STR + c]           = *(const uint4*)(qbh + r * DHD + c);
            *(uint4*)&smb[FA_QH_OFF + FA_QBUF + r * AT_STR + c] = *(const uint4*)(qbl + r * DHD + c);
        }
    }

    float accO[8][4] = {};
    float m0 = -1e30f, m1 = -1e30f, l0 = 0.f, l1 = 0.f;
    const int grow0 = qt * 128 + w * 16 + g;
    const int grow1 = grow0 + 8;

    const __nv_bfloat16* kbh = Kh + (size_t)bh * SEQ * DHD;
    const __nv_bfloat16* kbl = Kl + (size_t)bh * SEQ * DHD;
    const __nv_bfloat16* vbh = Vh + (size_t)bh * DHD * SEQ;
    const __nv_bfloat16* vbl = Vl + (size_t)bh * DHD * SEQ;

    const int ntiles = 2 * qt + 2;

    // prologue: stage tile 0 into stage 0
    {
        uint32_t stb = sbF;
        for (int i = 0; i < 2; i++) {
            int idx = tid + i * 256;
            int r = idx >> 3, c = (idx & 7) << 3;
            uint32_t so = stb + (r * AT_STR + c) * 2;
            cp_async16(so,                 kbh + (size_t)r * DHD + c);
            cp_async16(so + FA_BUF * 2,    kbl + (size_t)r * DHD + c);
            cp_async16(so + 2 * FA_BUF * 2, vbh + (size_t)r * SEQ + c);
            cp_async16(so + 3 * FA_BUF * 2, vbl + (size_t)r * SEQ + c);
        }
        CP_COMMIT();
    }

    for (int kt = 0; kt < ntiles; kt++) {
        const int cur = kt & 1;
        if (kt + 1 < ntiles) {
            uint32_t stb = sbF + (cur ^ 1) * FA_STAGE * 2;
            for (int i = 0; i < 2; i++) {
                int idx = tid + i * 256;
                int r = idx >> 3, c = (idx & 7) << 3;
                uint32_t so = stb + (r * AT_STR + c) * 2;
                cp_async16(so,                 kbh + (size_t)((kt + 1) * 64 + r) * DHD + c);
                cp_async16(so + FA_BUF * 2,    kbl + (size_t)((kt + 1) * 64 + r) * DHD + c);
                cp_async16(so + 2 * FA_BUF * 2, vbh + (size_t)r * SEQ + (kt + 1) * 64 + c);
                cp_async16(so + 3 * FA_BUF * 2, vbl + (size_t)r * SEQ + (kt + 1) * 64 + c);
            }
            CP_COMMIT();
            CP_WAIT1();
        } else {
            CP_WAIT0();
        }
        __syncthreads();   // also makes Q staging visible on first iteration

        const uint32_t sKhB = sbF + cur * FA_STAGE * 2;
        const uint32_t sKlB = sKhB + FA_BUF * 2;
        const uint32_t sVhB = sKhB + 2 * FA_BUF * 2;
        const uint32_t sVlB = sKhB + 3 * FA_BUF * 2;

        // S = Q @ K^T  (Q frags reloaded from smem; p-outer keeps only 16 Q regs live)
        float sc[8][4] = {};
#pragma unroll
        for (int p = 0; p < 2; p++) {
            uint32_t qh0[4], qh1[4], ql0[4], ql1[4];
            ldsm_x4(qh0, sbF + qfoff + p * 64);
            ldsm_x4(qh1, sbF + qfoff + p * 64 + 32);
            ldsm_x4(ql0, sbF + qfoff + FA_QBUF * 2 + p * 64);
            ldsm_x4(ql1, sbF + qfoff + FA_QBUF * 2 + p * 64 + 32);
#pragma unroll
            for (int nt = 0; nt < 8; nt++) {
                uint32_t rowb = (uint32_t)(nt * 8 * AT_STR * 2) + kboff;
                uint32_t bkh[4], bkl[4];
                ldsm_x4(bkh, sKhB + rowb + p * 64);
                ldsm_x4(bkl, sKlB + rowb + p * 64);
                mma16816(sc[nt], qh0, bkh);
                mma16816(sc[nt], qh0, bkl);
                mma16816(sc[nt], ql0, bkh);
                mma16816(sc[nt], qh1, bkh + 2);
                mma16816(sc[nt], qh1, bkl + 2);
                mma16816(sc[nt], ql1, bkh + 2);
            }
        }

        // causal mask on the last two tiles
        if (kt >= 2 * qt) {
#pragma unroll
            for (int nt = 0; nt < 8; nt++) {
                int keyg = kt * 64 + nt * 8 + tg * 2;
                if (keyg     > grow0) sc[nt][0] = -1e30f;
                if (keyg + 1 > grow0) sc[nt][1] = -1e30f;
                if (keyg     > grow1) sc[nt][2] = -1e30f;
                if (keyg + 1 > grow1) sc[nt][3] = -1e30f;
            }
        }

        // online softmax
        float mt0 = -1e30f, mt1 = -1e30f;
#pragma unroll
        for (int nt = 0; nt < 8; nt++) {
            mt0 = fmaxf(mt0, fmaxf(sc[nt][0], sc[nt][1]));
            mt1 = fmaxf(mt1, fmaxf(sc[nt][2], sc[nt][3]));
        }
        mt0 = fmaxf(mt0, __shfl_xor_sync(0xffffffffu, mt0, 1));
        mt0 = fmaxf(mt0, __shfl_xor_sync(0xffffffffu, mt0, 2));
        mt1 = fmaxf(mt1, __shfl_xor_sync(0xffffffffu, mt1, 1));
        mt1 = fmaxf(mt1, __shfl_xor_sync(0xffffffffu, mt1, 2));
        float mn0 = fmaxf(m0, mt0), mn1 = fmaxf(m1, mt1);
        float f0 = __expf(m0 - mn0), f1 = __expf(m1 - mn1);
        float s0 = 0.f, s1 = 0.f;
#pragma unroll
        for (int nt = 0; nt < 8; nt++) {
            float p0 = __expf(sc[nt][0] - mn0);
            float p1 = __expf(sc[nt][1] - mn0);
            float p2 = __expf(sc[nt][2] - mn1);
            float p3 = __expf(sc[nt][3] - mn1);
            sc[nt][0] = p0; sc[nt][1] = p1; sc[nt][2] = p2; sc[nt][3] = p3;
            s0 += p0 + p1; s1 += p2 + p3;
        }
        s0 += __shfl_xor_sync(0xffffffffu, s0, 1);
        s0 += __shfl_xor_sync(0xffffffffu, s0, 2);
        s1 += __shfl_xor_sync(0xffffffffu, s1, 1);
        s1 += __shfl_xor_sync(0xffffffffu, s1, 2);
        l0 = l0 * f0 + s0;
        l1 = l1 * f1 + s1;
        m0 = mn0; m1 = mn1;
#pragma unroll
        for (int dt = 0; dt < 8; dt++) {
            accO[dt][0] *= f0; accO[dt][1] *= f0;
            accO[dt][2] *= f1; accO[dt][3] *= f1;
        }

        // O += P @ V (P re-split hi/lo in registers; ldsm_x4 covers two k16 frags)
#pragma unroll
        for (int jp = 0; jp < 2; jp++) {
            uint32_t aPh[2][4], aPl[2][4];
#pragma unroll
            for (int jj = 0; jj < 2; jj++) {
                int j = jp * 2 + jj;
                float x00 = sc[2*j][0],   x01 = sc[2*j][1],   x02 = sc[2*j][2],   x03 = sc[2*j][3];
                float x10 = sc[2*j+1][0], x11 = sc[2*j+1][1], x12 = sc[2*j+1][2], x13 = sc[2*j+1][3];
                aPh[jj][0] = pack_bf16x2(x00, x01);
                aPh[jj][1] = pack_bf16x2(x02, x03);
                aPh[jj][2] = pack_bf16x2(x10, x11);
                aPh[jj][3] = pack_bf16x2(x12, x13);
                __nv_bfloat162* t;
                t = (__nv_bfloat162*)&aPh[jj][0];
                aPl[jj][0] = pack_bf16x2(x00 - __bfloat162float(t->x), x01 - __bfloat162float(t->y));
                t = (__nv_bfloat162*)&aPh[jj][1];
                aPl[jj][1] = pack_bf16x2(x02 - __bfloat162float(t->x), x03 - __bfloat162float(t->y));
                t = (__nv_bfloat162*)&aPh[jj][2];
                aPl[jj][2] = pack_bf16x2(x10 - __bfloat162float(t->x), x11 - __bfloat162float(t->y));
                t = (__nv_bfloat162*)&aPh[jj][3];
                aPl[jj][3] = pack_bf16x2(x12 - __bfloat162float(t->x), x13 - __bfloat162float(t->y));
            }
#pragma unroll
            for (int dt = 0; dt < 8; dt++) {
                uint32_t rb = (uint32_t)(dt * 8 * AT_STR * 2) + kboff + jp * 64;
                uint32_t bvh[4], bvl[4];
                ldsm_x4(bvh, sVhB + rb);
                ldsm_x4(bvl, sVlB + rb);
                mma16816(accO[dt], aPh[0], bvh);
                mma16816(accO[dt], aPh[0], bvl);
                mma16816(accO[dt], aPl[0], bvh);
                mma16816(accO[dt], aPh[1], bvh + 2);
                mma16816(accO[dt], aPh[1], bvl + 2);
                mma16816(accO[dt], aPl[1], bvh + 2);
            }
        }
        __syncthreads();
    }

    // epilogue -> (B,S,D) bf16 hi/lo
    float il0 = 1.0f / l0, il1 = 1.0f / l1;
    int b = bh >> 3, h = bh & 7;
    size_t row0 = (size_t)b * SEQ + qt * 128 + w * 16 + g;
    size_t row1 = row0 + 8;
#pragma unroll
    for (int dt = 0; dt < 8; dt++) {
        int col = h * DHD + dt * 8 + tg * 2;
        float o0 = accO[dt][0] * il0, o1 = accO[dt][1] * il0;
        float o2 = accO[dt][2] * il1, o3 = accO[dt][3] * il1;
        __nv_bfloat16 h0 = __float2bfloat16(o0), h1 = __float2bfloat16(o1);
        __nv_bfloat16 h2 = __float2bfloat16(o2), h3 = __float2bfloat16(o3);
        *(__nv_bfloat162*)(Ohi + row0 * DIM + col) = {h0, h1};
        *(__nv_bfloat162*)(Ohi + row1 * DIM + col) = {h2, h3};
        *(__nv_bfloat162*)(Olo + row0 * DIM + col) =
            {__float2bfloat16(o0 - __bfloat162float(h0)), __float2bfloat16(o1 - __bfloat162float(h1))};
        *(__nv_bfloat162*)(Olo + row1 * DIM + col) =
            {__float2bfloat16(o2 - __bfloat162float(h2)), __float2bfloat16(o3 - __bfloat162float(h3))};
    }
}

// ---------------- head: logits -> sigmoid probs ----------------
__global__ void head_kernel(const float* __restrict__ X, const float* __restrict__ hw,
                            const float* __restrict__ hb, float* __restrict__ probs) {
    int row = blockIdx.x * 8 + (threadIdx.x >> 5);
    int lane = threadIdx.x & 31;
    const float* xr = X + (size_t)row * DIM;
    float s = 0.f;
    for (int i = lane; i < DIM; i += 32) s = fmaf(xr[i], hw[i], s);
#pragma unroll
    for (int o = 16; o; o >>= 1) s += __shfl_xor_sync(0xffffffffu, s, o);
    if (lane == 0) {
        float logit = s + hb[0];
        probs[row] = 1.0f / (1.0f + expf(-logit));
    }
}

// ---------------- chunking (serial boundaries in smem, parallel id fill) ----------------
__global__ void chunk_kernel(const float* __restrict__ probs, int* __restrict__ ids,
                             int* __restrict__ nch, float* __restrict__ psum) {
    int b = blockIdx.x, t = threadIdx.x;
    __shared__ int flags[SEQ];
    __shared__ int ids_s[SEQ];
    __shared__ float red[256];
    const float* pr = probs + (size_t)b * SEQ;
    float s = 0.f; int any = 0;
    for (int i = t; i < SEQ; i += 256) {
        float p = pr[i];
        int f = (p > 0.5f) ? 1 : 0;
        flags[i] = f; s += p; any |= f;
    }
    red[t] = s;
    __syncthreads();
#pragma unroll
    for (int o = 128; o > 0; o >>= 1) {
        if (t < o) red[t] += red[t + o];
        __syncthreads();
    }
    int anyflag = __syncthreads_or(any);
    if (t == 0) {
        psum[b] = red[0];
        int cur_end = 0, cid = -1;
        for (int tt = 0; tt < SEQ; tt++) {
            if (tt == cur_end) {
                int cap = tt + 16; if (cap > SEQ) cap = SEQ;
                int e = cap;
                for (int ss = tt + 1; ss <= cap; ss++) {
                    int he = anyflag ? flags[ss - 1] : (ss == SEQ - 1);
                    if (he) { e = ss; break; }
                }
                if (e - tt < 3) { e = tt + 3; if (e > SEQ) e = SEQ; }
                cur_end = e; cid++;
            }
            ids_s[tt] = cid;
        }
        nch[b] = cid + 1;
    }
    __syncthreads();
    for (int i = t; i < SEQ; i += 256) ids[b * SEQ + i] = ids_s[i];
}

// ---------------- mask ----------------
__global__ void mask_kernel(const int* __restrict__ ids, float* __restrict__ out) {
    int i4 = blockIdx.x * 256 + threadIdx.x;
    int j = (i4 & 511) << 2;
    int rowIdx = i4 >> 9;
    int b = rowIdx >> 11;
    int idi = ids[rowIdx];
    const int* idr = ids + b * SEQ;
    size_t base = ((size_t)rowIdx << 11) + j;
    out[base + 0] = (idi == idr[j + 0]) ? 1.f : 0.f;
    out[base + 1] = (idi == idr[j + 1]) ? 1.f : 0.f;
    out[base + 2] = (idi == idr[j + 2]) ? 1.f : 0.f;
    out[base + 3] = (idi == idr[j + 3]) ? 1.f : 0.f;
}

__global__ void scalars_kernel(const int* __restrict__ nch, const float* __restrict__ psum,
                               float* __restrict__ out_acl, float* __restrict__ out_cll) {
    float a = 0.f, c = 0.f;
    for (int b = 0; b < NUM_B; b++) {
        a += (float)SEQ / (float)nch[b];
        c += psum[b];
    }
    *out_acl = a * 0.25f;
    *out_cll = c * 0.25f;
}

__global__ void xids_kernel(const int* __restrict__ xids, float* __restrict__ out) {
    int i = blockIdx.x * 256 + threadIdx.x;
    out[i] = (float)xids[i];
}

// ---------------- launch ----------------
extern "C" void kernel_launch(void* const* d_in, const int* in_sizes, int n_in,
                              void* d_out, int out_size) {
    const float* x    = (const float*)d_in[0];
    const int*   xids = (const int*)  d_in[1];
    const float* ln1  = (const float*)d_in[2];
    const float* Wq   = (const float*)d_in[3];
    const float* Wk   = (const float*)d_in[4];
    const float* Wv   = (const float*)d_in[5];
    const float* Wo   = (const float*)d_in[6];
    const float* ln2  = (const float*)d_in[7];
    const float* W1   = (const float*)d_in[8];
    const float* W2   = (const float*)d_in[9];
    const float* hw   = (const float*)d_in[10];
    const float* hb   = (const float*)d_in[11];
    float* out = (float*)d_out;

    float *X, *probs, *psum, *rc, *rs;
    __nv_bfloat16 *Ahi, *Alo, *Ghi, *Glo, *WThi, *WTlo;
    __nv_bfloat16 *Qbh, *Qbl, *Kbh, *Kbl, *Vbh, *Vbl;
    int *ids, *nch;
    cudaGetSymbolAddress((void**)&X,  g_X);
    cudaGetSymbolAddress((void**)&Qbh, g_Qbh);
    cudaGetSymbolAddress((void**)&Qbl, g_Qbl);
    cudaGetSymbolAddress((void**)&Kbh, g_Kbh);
    cudaGetSymbolAddress((void**)&Kbl, g_Kbl);
    cudaGetSymbolAddress((void**)&Vbh, g_Vbh);
    cudaGetSymbolAddress((void**)&Vbl, g_Vbl);
    cudaGetSymbolAddress((void**)&Ahi, g_Ahi);
    cudaGetSymbolAddress((void**)&Alo, g_Alo);
    cudaGetSymbolAddress((void**)&Ghi, g_Ghi);
    cudaGetSymbolAddress((void**)&Glo, g_Glo);
    cudaGetSymbolAddress((void**)&WThi, g_WThi);
    cudaGetSymbolAddress((void**)&WTlo, g_WTlo);
    cudaGetSymbolAddress((void**)&probs, g_probs);
    cudaGetSymbolAddress((void**)&psum,  g_psum);
    cudaGetSymbolAddress((void**)&ids, g_ids);
    cudaGetSymbolAddress((void**)&nch, g_nch);
    cudaGetSymbolAddress((void**)&rc, g_rc);
    cudaGetSymbolAddress((void**)&rs, g_rs);

    cudaFuncSetAttribute(hmma_gemm_kernel<1>, cudaFuncAttributeMaxDynamicSharedMemorySize, GM_SMEM2);
    cudaFuncSetAttribute(hmma_gemm_kernel<3>, cudaFuncAttributeMaxDynamicSharedMemorySize, GM_SMEM2);
    cudaFuncSetAttribute(hmma_gemm_qkv, cudaFuncAttributeMaxDynamicSharedMemorySize, GM_SMEM2);
    cudaFuncSetAttribute(fa_kernel, cudaFuncAttributeMaxDynamicSharedMemorySize, FA_SMEM);

    // fused prep: rope table + all weight transposes/splits in one launch
    prep_kernel<<<256 + NLAYER * 3072, 256>>>(Wq, Wk, Wv, Wo, W1, W2, WThi, WTlo, rc, rs);
    cudaMemcpyAsync(X, x, sizeof(float) * (size_t)ROWS * DIM, cudaMemcpyDeviceToDevice, 0);

    dim3 g512(DIM / 128, ROWS / 128);   // (4, 64)
    dim3 gqkv(12, ROWS / 128);          // fused QKV: 3 x 4 n-blocks
    dim3 gff (FF  / 128, ROWS / 128);   // (16, 64)
    dim3 gfa (NUM_B * NH, SEQ / 128);   // bh fastest, qt reversed inside

    for (int l = 0; l < NLAYER; l++) {
        const __nv_bfloat16* th = WThi + (size_t)l * WT_LAYER;
        const __nv_bfloat16* tl = WTlo + (size_t)l * WT_LAYER;

        rmsnorm_split_kernel<<<ROWS / 8, 256>>>(X, ln1 + l * DIM, Ahi, Alo);
        hmma_gemm_qkv<<<gqkv, 256, GM_SMEM2>>>(Ahi, Alo, th, tl,
                                               Qbh, Qbl, Kbh, Kbl, Vbh, Vbl, rc, rs);
        fa_kernel<<<gfa, 256, FA_SMEM>>>(Qbh, Qbl, Kbh, Kbl, Vbh, Vbl, Ahi, Alo);
        hmma_gemm_kernel<1><<<g512, 256, GM_SMEM2>>>(Ahi, Alo, th + WT_O, tl + WT_O,
                                                     X, X, nullptr, nullptr, ROWS, DIM, DIM);
        rmsnorm_split_kernel<<<ROWS / 8, 256>>>(X, ln2 + l * DIM, Ahi, Alo);
        hmma_gemm_kernel<3><<<gff, 256, GM_SMEM2>>>(Ahi, Alo, th + WT_W1, tl + WT_W1,
                                                    nullptr, nullptr, Ghi, Glo, ROWS, FF, DIM);
        hmma_gemm_kernel<1><<<g512, 256, GM_SMEM2>>>(Ghi, Glo, th + WT_W2, tl + WT_W2,
                                                     X, X, nullptr, nullptr, ROWS, DIM, FF);
    }

    head_kernel <<<ROWS / 8, 256>>>(X, hw, hb, probs);
    chunk_kernel<<<NUM_B, 256>>>(probs, ids, nch, psum);
    mask_kernel <<<(N_MASK / 4) / 256, 256>>>(ids, out + OFF_MASK);
    scalars_kernel<<<1, 1>>>(nch, psum, out + OFF_ACL, out + OFF_CLL);
    xids_kernel <<<ROWS / 256, 256>>>(xids, out + OFF_IDS);
    cudaMemcpyAsync(out + OFF_XT, X, sizeof(float) * (size_t)ROWS * DIM, cudaMemcpyDeviceToDevice, 0);
}